// round 3
// baseline (speedup 1.0000x reference)
#include <cuda_runtime.h>
#include <math.h>

// Problem constants (fixed by setup_inputs)
#define N_NODES 32768
#define E_EDGES 524288
#define F_IN    128
#define D1      256
#define D2      128
#define NT      3
#define SEQ     16
#define NNG     512   // nodes per graph

// ---------------- scratch (device globals; no allocation allowed) ----------------
__device__ float  g_xn  [N_NODES * F_IN];            // 16 MB normalized x
__device__ float  g_agg [NT * N_NODES * F_IN];       // 48 MB aggregated xn per type
__device__ float  g_h1r [NT * N_NODES * D1];         // 96 MB relu(agg@W1+b1) per type
__device__ float  g_h2  [NT * N_NODES * D2];         // 48 MB h1r@W2 per type
__device__ float  g_deg [NT * N_NODES];
__device__ float  g_dis [NT * N_NODES];
__device__ int    g_counts[N_NODES];
__device__ int    g_rowptr[N_NODES + 1];
__device__ int    g_cursor[N_NODES];
__device__ float4 g_meta[E_EDGES];                   // 8 MB {w0,w1,w2,src-as-float} CSR by dst
__device__ float  g_colsum[F_IN];
__device__ float  g_colsq [F_IN];
__device__ float  g_mean[F_IN];
__device__ float  g_rstd[F_IN];

// ---------------- f32x2 packed-FMA helpers ----------------
__device__ __forceinline__ void ffma2(unsigned long long& acc,
                                      unsigned long long a, unsigned long long b) {
    asm("fma.rn.f32x2 %0, %1, %2, %0;" : "+l"(acc) : "l"(a), "l"(b));
}
__device__ __forceinline__ float2 unpack2(unsigned long long v) {
    unsigned lo, hi;
    asm("mov.b64 {%0, %1}, %2;" : "=r"(lo), "=r"(hi) : "l"(v));
    return make_float2(__uint_as_float(lo), __uint_as_float(hi));
}

// ---------------- small prep kernels ----------------
__global__ void zero_kernel() {
    int i = blockIdx.x * 256 + threadIdx.x;            // grid 384*256 = 98304
    if (i < N_NODES)      g_counts[i] = 0;
    if (i < NT * N_NODES) g_deg[i] = 0.0f;
    if (i < F_IN) { g_colsum[i] = 0.0f; g_colsq[i] = 0.0f; }
}

__global__ void stats_kernel(const float* __restrict__ x) {
    int c  = threadIdx.x;
    int r0 = blockIdx.x * 256;
    float s = 0.0f, q = 0.0f;
    for (int r = 0; r < 256; r++) {
        float v = x[(r0 + r) * F_IN + c];
        s += v; q += v * v;
    }
    atomicAdd(&g_colsum[c], s);
    atomicAdd(&g_colsq[c],  q);
}

__global__ void finstats_kernel() {
    int c = threadIdx.x;
    float n = (float)N_NODES;
    float mean = g_colsum[c] / n;
    float var  = (g_colsq[c] - n * mean * mean) / (n - 1.0f);  // ddof=1
    g_mean[c] = mean;
    g_rstd[c] = rsqrtf(var);
}

__global__ void normalize_kernel(const float* __restrict__ x) {
    int i  = blockIdx.x * 256 + threadIdx.x;  // float4 index
    int c4 = (i & 31) * 4;
    float4 v = ((const float4*)x)[i];
    v.x = (v.x - g_mean[c4 + 0]) * g_rstd[c4 + 0];
    v.y = (v.y - g_mean[c4 + 1]) * g_rstd[c4 + 1];
    v.z = (v.z - g_mean[c4 + 2]) * g_rstd[c4 + 2];
    v.w = (v.w - g_mean[c4 + 3]) * g_rstd[c4 + 3];
    ((float4*)g_xn)[i] = v;
}

__global__ void hist_kernel(const int* __restrict__ ei, const float* __restrict__ ea) {
    int e = blockIdx.x * 256 + threadIdx.x;
    if (e >= E_EDGES) return;
    int dst = ei[E_EDGES + e];
    atomicAdd(&g_counts[dst], 1);
    atomicAdd(&g_deg[0 * N_NODES + dst], fabsf(ea[3 * e + 0]));
    atomicAdd(&g_deg[1 * N_NODES + dst], fabsf(ea[3 * e + 1]));
    atomicAdd(&g_deg[2 * N_NODES + dst], fabsf(ea[3 * e + 2]));
}

__global__ void scan_kernel() {
    __shared__ int sums[1024];
    int tid  = threadIdx.x;
    int base = tid * 32;
    int vals[32];
    int s = 0;
#pragma unroll
    for (int i = 0; i < 32; i++) { int v = g_counts[base + i]; vals[i] = s; s += v; }
    sums[tid] = s;
    __syncthreads();
    for (int off = 1; off < 1024; off <<= 1) {
        int v = (tid >= off) ? sums[tid - off] : 0;
        __syncthreads();
        sums[tid] += v;
        __syncthreads();
    }
    int ex = (tid > 0) ? sums[tid - 1] : 0;
#pragma unroll
    for (int i = 0; i < 32; i++) {
        int p = ex + vals[i];
        g_rowptr[base + i] = p;
        g_cursor[base + i] = p;
    }
    if (tid == 1023) g_rowptr[N_NODES] = sums[1023];
}

__global__ void dis_kernel() {
    int i = blockIdx.x * 256 + threadIdx.x;
    if (i < NT * N_NODES) g_dis[i] = rsqrtf(g_deg[i] + 1.0f);
}

// scatter edges into CSR order; pack per-edge {normalized w0,w1,w2, src}
__global__ void fill_kernel(const int* __restrict__ ei, const float* __restrict__ ea) {
    int e = blockIdx.x * 256 + threadIdx.x;
    if (e >= E_EDGES) return;
    int src = ei[e];
    int dst = ei[E_EDGES + e];
    int pos = atomicAdd(&g_cursor[dst], 1);
    float4 m;
    m.x = g_dis[0 * N_NODES + src] * fabsf(ea[3 * e + 0]) * g_dis[0 * N_NODES + dst];
    m.y = g_dis[1 * N_NODES + src] * fabsf(ea[3 * e + 1]) * g_dis[1 * N_NODES + dst];
    m.z = g_dis[2 * N_NODES + src] * fabsf(ea[3 * e + 2]) * g_dis[2 * N_NODES + dst];
    m.w = __int_as_float(src);
    g_meta[pos] = m;
}

// ---------------- fused 3-type aggregation of xn (gather, atomic-free) ----------------
__global__ void gather0_kernel() {
    int lane = threadIdx.x & 31;
    int v    = blockIdx.x * 8 + (threadIdx.x >> 5);   // 4096 blocks * 8 warps

    const float4* __restrict__ xn4 = (const float4*)g_xn;
    int beg = g_rowptr[v];
    int end = g_rowptr[v + 1];

    float4 a0 = make_float4(0.f, 0.f, 0.f, 0.f);
    float4 a1 = make_float4(0.f, 0.f, 0.f, 0.f);
    float4 a2 = make_float4(0.f, 0.f, 0.f, 0.f);

    int j = beg;
    for (; j + 1 < end; j += 2) {
        float4 mA = __ldg(&g_meta[j]);
        float4 mB = __ldg(&g_meta[j + 1]);
        float4 xA = xn4[__float_as_int(mA.w) * 32 + lane];
        float4 xB = xn4[__float_as_int(mB.w) * 32 + lane];
        a0.x = fmaf(mA.x, xA.x, a0.x); a0.y = fmaf(mA.x, xA.y, a0.y);
        a0.z = fmaf(mA.x, xA.z, a0.z); a0.w = fmaf(mA.x, xA.w, a0.w);
        a1.x = fmaf(mA.y, xA.x, a1.x); a1.y = fmaf(mA.y, xA.y, a1.y);
        a1.z = fmaf(mA.y, xA.z, a1.z); a1.w = fmaf(mA.y, xA.w, a1.w);
        a2.x = fmaf(mA.z, xA.x, a2.x); a2.y = fmaf(mA.z, xA.y, a2.y);
        a2.z = fmaf(mA.z, xA.z, a2.z); a2.w = fmaf(mA.z, xA.w, a2.w);
        a0.x = fmaf(mB.x, xB.x, a0.x); a0.y = fmaf(mB.x, xB.y, a0.y);
        a0.z = fmaf(mB.x, xB.z, a0.z); a0.w = fmaf(mB.x, xB.w, a0.w);
        a1.x = fmaf(mB.y, xB.x, a1.x); a1.y = fmaf(mB.y, xB.y, a1.y);
        a1.z = fmaf(mB.y, xB.z, a1.z); a1.w = fmaf(mB.y, xB.w, a1.w);
        a2.x = fmaf(mB.z, xB.x, a2.x); a2.y = fmaf(mB.z, xB.y, a2.y);
        a2.z = fmaf(mB.z, xB.z, a2.z); a2.w = fmaf(mB.z, xB.w, a2.w);
    }
    if (j < end) {
        float4 m = __ldg(&g_meta[j]);
        float4 x = xn4[__float_as_int(m.w) * 32 + lane];
        a0.x = fmaf(m.x, x.x, a0.x); a0.y = fmaf(m.x, x.y, a0.y);
        a0.z = fmaf(m.x, x.z, a0.z); a0.w = fmaf(m.x, x.w, a0.w);
        a1.x = fmaf(m.y, x.x, a1.x); a1.y = fmaf(m.y, x.y, a1.y);
        a1.z = fmaf(m.y, x.z, a1.z); a1.w = fmaf(m.y, x.w, a1.w);
        a2.x = fmaf(m.z, x.x, a2.x); a2.y = fmaf(m.z, x.y, a2.y);
        a2.z = fmaf(m.z, x.z, a2.z); a2.w = fmaf(m.z, x.w, a2.w);
    }

    float4 xv = xn4[v * 32 + lane];
    float i0 = g_dis[0 * N_NODES + v]; i0 *= i0;
    float i1 = g_dis[1 * N_NODES + v]; i1 *= i1;
    float i2 = g_dis[2 * N_NODES + v]; i2 *= i2;
    a0.x = fmaf(i0, xv.x, a0.x); a0.y = fmaf(i0, xv.y, a0.y);
    a0.z = fmaf(i0, xv.z, a0.z); a0.w = fmaf(i0, xv.w, a0.w);
    a1.x = fmaf(i1, xv.x, a1.x); a1.y = fmaf(i1, xv.y, a1.y);
    a1.z = fmaf(i1, xv.z, a1.z); a1.w = fmaf(i1, xv.w, a1.w);
    a2.x = fmaf(i2, xv.x, a2.x); a2.y = fmaf(i2, xv.y, a2.y);
    a2.z = fmaf(i2, xv.z, a2.z); a2.w = fmaf(i2, xv.w, a2.w);

    float4* o = (float4*)g_agg;
    o[(0 * N_NODES + v) * 32 + lane] = a0;
    o[(1 * N_NODES + v) * 32 + lane] = a1;
    o[(2 * N_NODES + v) * 32 + lane] = a2;
}

// ---------------- f32x2 GEMM with duplicated-A smem (no pack MOVs) ----------------
// C[M,N] = A[M,K] @ W[K,N] (+bias, relu). BM=BN=128, BK=16, 256 threads, 8x8 microtile.
// As2[k][2m] = As2[k][2m+1] = A[m][k]  -> LDS.128 yields two ready-packed u64 operands.
#define AS2_STRIDE 260   // 16B-aligned rows (260*4=1040), small write-conflict amortized
__global__ void __launch_bounds__(256, 2) gemm_f32x2(
    const float* __restrict__ Abase, long long Astride,
    const float* __restrict__ Wbase, long long Wstride,
    float* __restrict__ Cbase, long long Cstride,
    const float* __restrict__ biasBase, int biasStride,
    int M, int N, int K, int doRelu)
{
    __shared__ float As2[16][AS2_STRIDE];
    __shared__ float Bs[16][128];

    const int t   = blockIdx.z;
    const float* A = Abase + (long long)t * Astride;
    const float* W = Wbase + (long long)t * Wstride;
    float*       C = Cbase + (long long)t * Cstride;

    const int tid = threadIdx.x;
    const int tm  = (tid >> 4) * 8;     // 0..120
    const int tn  = (tid & 15) * 8;     // 0..120
    const int bm0 = blockIdx.y * 128;
    const int bn0 = blockIdx.x * 128;

    const int a_r = tid >> 2;           // 0..63 (rows a_r, a_r+64)
    const int a_k = (tid & 3) * 4;
    const int b_r = tid >> 5;           // 0..7 (rows b_r, b_r+8)
    const int b_c = (tid & 31) * 4;

    unsigned long long acc[8][4];
#pragma unroll
    for (int i = 0; i < 8; i++)
#pragma unroll
        for (int j = 0; j < 4; j++) acc[i][j] = 0ULL;

    float4 aReg[2], bReg[2];

    // prologue k0 = 0
    aReg[0] = *(const float4*)(A + (long long)(bm0 + a_r)      * K + a_k);
    aReg[1] = *(const float4*)(A + (long long)(bm0 + a_r + 64) * K + a_k);
    bReg[0] = *(const float4*)(W + (long long)(b_r)     * N + bn0 + b_c);
    bReg[1] = *(const float4*)(W + (long long)(b_r + 8) * N + bn0 + b_c);

    {
        const float av0[4] = {aReg[0].x, aReg[0].y, aReg[0].z, aReg[0].w};
        const float av1[4] = {aReg[1].x, aReg[1].y, aReg[1].z, aReg[1].w};
#pragma unroll
        for (int kk = 0; kk < 4; kk++) {
            *(float2*)&As2[a_k + kk][2 * a_r]        = make_float2(av0[kk], av0[kk]);
            *(float2*)&As2[a_k + kk][2 * (a_r + 64)] = make_float2(av1[kk], av1[kk]);
        }
    }
    *(float4*)&Bs[b_r][b_c]     = bReg[0];
    *(float4*)&Bs[b_r + 8][b_c] = bReg[1];
    __syncthreads();

    for (int k0 = 16;; k0 += 16) {
        bool more = (k0 < K);
        if (more) {
            aReg[0] = *(const float4*)(A + (long long)(bm0 + a_r)      * K + k0 + a_k);
            aReg[1] = *(const float4*)(A + (long long)(bm0 + a_r + 64) * K + k0 + a_k);
            bReg[0] = *(const float4*)(W + (long long)(k0 + b_r)     * N + bn0 + b_c);
            bReg[1] = *(const float4*)(W + (long long)(k0 + b_r + 8) * N + bn0 + b_c);
        }
#pragma unroll
        for (int k = 0; k < 16; k++) {
            ulonglong2 a01 = *(const ulonglong2*)&As2[k][2 * tm];
            ulonglong2 a23 = *(const ulonglong2*)&As2[k][2 * tm + 4];
            ulonglong2 a45 = *(const ulonglong2*)&As2[k][2 * tm + 8];
            ulonglong2 a67 = *(const ulonglong2*)&As2[k][2 * tm + 12];
            ulonglong2 b01 = *(const ulonglong2*)&Bs[k][tn];
            ulonglong2 b23 = *(const ulonglong2*)&Bs[k][tn + 4];
            unsigned long long a[8] = {a01.x, a01.y, a23.x, a23.y,
                                       a45.x, a45.y, a67.x, a67.y};
            unsigned long long b[4] = {b01.x, b01.y, b23.x, b23.y};
#pragma unroll
            for (int i = 0; i < 8; i++) {
                ffma2(acc[i][0], a[i], b[0]);
                ffma2(acc[i][1], a[i], b[1]);
                ffma2(acc[i][2], a[i], b[2]);
                ffma2(acc[i][3], a[i], b[3]);
            }
        }
        if (!more) break;
        __syncthreads();
        {
            const float av0[4] = {aReg[0].x, aReg[0].y, aReg[0].z, aReg[0].w};
            const float av1[4] = {aReg[1].x, aReg[1].y, aReg[1].z, aReg[1].w};
#pragma unroll
            for (int kk = 0; kk < 4; kk++) {
                *(float2*)&As2[a_k + kk][2 * a_r]        = make_float2(av0[kk], av0[kk]);
                *(float2*)&As2[a_k + kk][2 * (a_r + 64)] = make_float2(av1[kk], av1[kk]);
            }
        }
        *(float4*)&Bs[b_r][b_c]     = bReg[0];
        *(float4*)&Bs[b_r + 8][b_c] = bReg[1];
        __syncthreads();
    }

    float bias[8];
    if (biasBase) {
        const float* bp = biasBase + (long long)t * biasStride + bn0 + tn;
        *(float4*)&bias[0] = *(const float4*)(bp);
        *(float4*)&bias[4] = *(const float4*)(bp + 4);
    } else {
#pragma unroll
        for (int j = 0; j < 8; j++) bias[j] = 0.0f;
    }

#pragma unroll
    for (int i = 0; i < 8; i++) {
        float o[8];
#pragma unroll
        for (int j = 0; j < 4; j++) {
            float2 p = unpack2(acc[i][j]);
            o[2 * j]     = p.x + bias[2 * j];
            o[2 * j + 1] = p.y + bias[2 * j + 1];
        }
        if (doRelu) {
#pragma unroll
            for (int j = 0; j < 8; j++) o[j] = fmaxf(o[j], 0.0f);
        }
        float* cp = C + (long long)(bm0 + tm + i) * N + bn0 + tn;
        *(float4*)(cp)     = *(float4*)&o[0];
        *(float4*)(cp + 4) = *(float4*)&o[4];
    }
}

// ---------------- layer-2 gather: all 3 types fused, + output permutation ----------------
__global__ void gather2_kernel(const float* __restrict__ b2, float* __restrict__ out) {
    int lane = threadIdx.x & 31;
    int v    = blockIdx.x * 8 + (threadIdx.x >> 5);

    const float4* __restrict__ h2a = (const float4*)(g_h2);
    const float4* __restrict__ h2b = (const float4*)(g_h2 + (long long)N_NODES * D2);
    const float4* __restrict__ h2c = (const float4*)(g_h2 + 2LL * N_NODES * D2);
    int beg = g_rowptr[v];
    int end = g_rowptr[v + 1];

    float4 a0 = make_float4(0.f, 0.f, 0.f, 0.f);
    float4 a1 = make_float4(0.f, 0.f, 0.f, 0.f);
    float4 a2 = make_float4(0.f, 0.f, 0.f, 0.f);

    for (int j = beg; j < end; j++) {
        float4 m = __ldg(&g_meta[j]);
        int src = __float_as_int(m.w);
        float4 x0 = h2a[src * 32 + lane];
        float4 x1 = h2b[src * 32 + lane];
        float4 x2 = h2c[src * 32 + lane];
        a0.x = fmaf(m.x, x0.x, a0.x); a0.y = fmaf(m.x, x0.y, a0.y);
        a0.z = fmaf(m.x, x0.z, a0.z); a0.w = fmaf(m.x, x0.w, a0.w);
        a1.x = fmaf(m.y, x1.x, a1.x); a1.y = fmaf(m.y, x1.y, a1.y);
        a1.z = fmaf(m.y, x1.z, a1.z); a1.w = fmaf(m.y, x1.w, a1.w);
        a2.x = fmaf(m.z, x2.x, a2.x); a2.y = fmaf(m.z, x2.y, a2.y);
        a2.z = fmaf(m.z, x2.z, a2.z); a2.w = fmaf(m.z, x2.w, a2.w);
    }

    float i0 = g_dis[0 * N_NODES + v]; i0 *= i0;
    float i1 = g_dis[1 * N_NODES + v]; i1 *= i1;
    float i2 = g_dis[2 * N_NODES + v]; i2 *= i2;
    float4 s0 = h2a[v * 32 + lane];
    float4 s1 = h2b[v * 32 + lane];
    float4 s2 = h2c[v * 32 + lane];
    float4 bb0 = ((const float4*)(b2 + 0 * D2))[lane];
    float4 bb1 = ((const float4*)(b2 + 1 * D2))[lane];
    float4 bb2 = ((const float4*)(b2 + 2 * D2))[lane];

    a0.x = fmaxf(fmaf(i0, s0.x, a0.x) + bb0.x, 0.f);
    a0.y = fmaxf(fmaf(i0, s0.y, a0.y) + bb0.y, 0.f);
    a0.z = fmaxf(fmaf(i0, s0.z, a0.z) + bb0.z, 0.f);
    a0.w = fmaxf(fmaf(i0, s0.w, a0.w) + bb0.w, 0.f);
    a1.x = fmaxf(fmaf(i1, s1.x, a1.x) + bb1.x, 0.f);
    a1.y = fmaxf(fmaf(i1, s1.y, a1.y) + bb1.y, 0.f);
    a1.z = fmaxf(fmaf(i1, s1.z, a1.z) + bb1.z, 0.f);
    a1.w = fmaxf(fmaf(i1, s1.w, a1.w) + bb1.w, 0.f);
    a2.x = fmaxf(fmaf(i2, s2.x, a2.x) + bb2.x, 0.f);
    a2.y = fmaxf(fmaf(i2, s2.y, a2.y) + bb2.y, 0.f);
    a2.z = fmaxf(fmaf(i2, s2.z, a2.z) + bb2.z, 0.f);
    a2.w = fmaxf(fmaf(i2, s2.w, a2.w) + bb2.w, 0.f);

    // node v = ((bt*SEQ + sq)*NNG + vv) -> out[(bt*NNG+vv), sq, t*D2 + d]
    int bt = v >> 13;
    int sq = (v >> 9) & 15;
    int vv = v & 511;
    int orow = bt * NNG + vv;
    long long base = ((long long)(orow * SEQ + sq)) * (NT * D2) + lane * 4;
    *(float4*)(out + base)          = a0;
    *(float4*)(out + base + D2)     = a1;
    *(float4*)(out + base + 2 * D2) = a2;
}

// ---------------- launch ----------------
extern "C" void kernel_launch(void* const* d_in, const int* in_sizes, int n_in,
                              void* d_out, int out_size) {
    const float* x  = (const float*)d_in[0];
    const float* ea = (const float*)d_in[1];
    const float* W1 = (const float*)d_in[2];
    const float* b1 = (const float*)d_in[3];
    const float* W2 = (const float*)d_in[4];
    const float* b2 = (const float*)d_in[5];
    const int*   ei = (const int*)d_in[6];
    float* out = (float*)d_out;

    float *agg, *h1r, *h2;
    cudaGetSymbolAddress((void**)&agg, g_agg);
    cudaGetSymbolAddress((void**)&h1r, g_h1r);
    cudaGetSymbolAddress((void**)&h2,  g_h2);

    zero_kernel     <<<384, 256>>>();
    stats_kernel    <<<128, 128>>>(x);
    finstats_kernel <<<1, 128>>>();
    normalize_kernel<<<4096, 256>>>(x);
    hist_kernel     <<<E_EDGES / 256, 256>>>(ei, ea);
    scan_kernel     <<<1, 1024>>>();
    dis_kernel      <<<384, 256>>>();
    fill_kernel     <<<E_EDGES / 256, 256>>>(ei, ea);
    gather0_kernel  <<<N_NODES / 8, 256>>>();

    // h1r_t = relu(agg_t @ W1_t + b1_t)   [32768,128]@[128,256], all 3 types in z
    gemm_f32x2<<<dim3(D1 / 128, N_NODES / 128, NT), 256>>>(
        agg, (long long)N_NODES * F_IN, W1, (long long)F_IN * D1,
        h1r, (long long)N_NODES * D1, b1, D1,
        N_NODES, D1, F_IN, 1);

    // h2_t = h1r_t @ W2_t   [32768,256]@[256,128]
    gemm_f32x2<<<dim3(D2 / 128, N_NODES / 128, NT), 256>>>(
        h1r, (long long)N_NODES * D1, W2, (long long)D1 * D2,
        h2, (long long)N_NODES * D2, (const float*)nullptr, 0,
        N_NODES, D2, D1, 0);

    gather2_kernel<<<N_NODES / 8, 256>>>(b2, out);
}

// round 4
// speedup vs baseline: 1.0658x; 1.0658x over previous
#include <cuda_runtime.h>
#include <math.h>

// Problem constants (fixed by setup_inputs)
#define N_NODES 32768
#define E_EDGES 524288
#define F_IN    128
#define D1      256
#define D2      128
#define NT      3
#define SEQ     16
#define NNG     512   // nodes per graph

// ---------------- scratch (device globals; no allocation allowed) ----------------
__device__ float  g_xn  [N_NODES * F_IN];
__device__ float  g_agg [NT * N_NODES * F_IN];
__device__ float  g_h1r [NT * N_NODES * D1];
__device__ float  g_h2  [NT * N_NODES * D2];
__device__ float  g_deg [NT * N_NODES];
__device__ float  g_dis [NT * N_NODES];
__device__ int    g_counts[N_NODES];
__device__ int    g_rowptr[N_NODES + 1];
__device__ int    g_cursor[N_NODES];
__device__ float4 g_meta[E_EDGES];                   // {w0,w1,w2,src-as-float} CSR by dst
__device__ float  g_colsum[F_IN];
__device__ float  g_colsq [F_IN];
__device__ float  g_mean[F_IN];
__device__ float  g_rstd[F_IN];

// ---------------- f32x2 packed-FMA helpers ----------------
__device__ __forceinline__ unsigned long long pack2(float x) {
    unsigned long long r;
    asm("mov.b64 %0, {%1, %1};" : "=l"(r) : "r"(__float_as_uint(x)));
    return r;
}
__device__ __forceinline__ void ffma2(unsigned long long& acc,
                                      unsigned long long a, unsigned long long b) {
    asm("fma.rn.f32x2 %0, %1, %2, %0;" : "+l"(acc) : "l"(a), "l"(b));
}
__device__ __forceinline__ float2 unpack2(unsigned long long v) {
    unsigned lo, hi;
    asm("mov.b64 {%0, %1}, %2;" : "=r"(lo), "=r"(hi) : "l"(v));
    return make_float2(__uint_as_float(lo), __uint_as_float(hi));
}

// ---------------- small prep kernels ----------------
__global__ void zero_kernel() {
    int i = blockIdx.x * 256 + threadIdx.x;
    if (i < N_NODES)      g_counts[i] = 0;
    if (i < NT * N_NODES) g_deg[i] = 0.0f;
    if (i < F_IN) { g_colsum[i] = 0.0f; g_colsq[i] = 0.0f; }
}

__global__ void stats_kernel(const float* __restrict__ x) {
    int c  = threadIdx.x;
    int r0 = blockIdx.x * 256;
    float s = 0.0f, q = 0.0f;
    for (int r = 0; r < 256; r++) {
        float v = x[(r0 + r) * F_IN + c];
        s += v; q += v * v;
    }
    atomicAdd(&g_colsum[c], s);
    atomicAdd(&g_colsq[c],  q);
}

__global__ void finstats_kernel() {
    int c = threadIdx.x;
    float n = (float)N_NODES;
    float mean = g_colsum[c] / n;
    float var  = (g_colsq[c] - n * mean * mean) / (n - 1.0f);  // ddof=1
    g_mean[c] = mean;
    g_rstd[c] = rsqrtf(var);
}

__global__ void normalize_kernel(const float* __restrict__ x) {
    int i  = blockIdx.x * 256 + threadIdx.x;
    int c4 = (i & 31) * 4;
    float4 v = ((const float4*)x)[i];
    v.x = (v.x - g_mean[c4 + 0]) * g_rstd[c4 + 0];
    v.y = (v.y - g_mean[c4 + 1]) * g_rstd[c4 + 1];
    v.z = (v.z - g_mean[c4 + 2]) * g_rstd[c4 + 2];
    v.w = (v.w - g_mean[c4 + 3]) * g_rstd[c4 + 3];
    ((float4*)g_xn)[i] = v;
}

__global__ void hist_kernel(const int* __restrict__ ei, const float* __restrict__ ea) {
    int e = blockIdx.x * 256 + threadIdx.x;
    if (e >= E_EDGES) return;
    int dst = ei[E_EDGES + e];
    atomicAdd(&g_counts[dst], 1);
    atomicAdd(&g_deg[0 * N_NODES + dst], fabsf(ea[3 * e + 0]));
    atomicAdd(&g_deg[1 * N_NODES + dst], fabsf(ea[3 * e + 1]));
    atomicAdd(&g_deg[2 * N_NODES + dst], fabsf(ea[3 * e + 2]));
}

__global__ void scan_kernel() {
    __shared__ int sums[1024];
    int tid  = threadIdx.x;
    int base = tid * 32;
    int vals[32];
    int s = 0;
#pragma unroll
    for (int i = 0; i < 32; i++) { int v = g_counts[base + i]; vals[i] = s; s += v; }
    sums[tid] = s;
    __syncthreads();
    for (int off = 1; off < 1024; off <<= 1) {
        int v = (tid >= off) ? sums[tid - off] : 0;
        __syncthreads();
        sums[tid] += v;
        __syncthreads();
    }
    int ex = (tid > 0) ? sums[tid - 1] : 0;
#pragma unroll
    for (int i = 0; i < 32; i++) {
        int p = ex + vals[i];
        g_rowptr[base + i] = p;
        g_cursor[base + i] = p;
    }
    if (tid == 1023) g_rowptr[N_NODES] = sums[1023];
}

__global__ void dis_kernel() {
    int i = blockIdx.x * 256 + threadIdx.x;
    if (i < NT * N_NODES) g_dis[i] = rsqrtf(g_deg[i] + 1.0f);
}

__global__ void fill_kernel(const int* __restrict__ ei, const float* __restrict__ ea) {
    int e = blockIdx.x * 256 + threadIdx.x;
    if (e >= E_EDGES) return;
    int src = ei[e];
    int dst = ei[E_EDGES + e];
    int pos = atomicAdd(&g_cursor[dst], 1);
    float4 m;
    m.x = g_dis[0 * N_NODES + src] * fabsf(ea[3 * e + 0]) * g_dis[0 * N_NODES + dst];
    m.y = g_dis[1 * N_NODES + src] * fabsf(ea[3 * e + 1]) * g_dis[1 * N_NODES + dst];
    m.z = g_dis[2 * N_NODES + src] * fabsf(ea[3 * e + 2]) * g_dis[2 * N_NODES + dst];
    m.w = __int_as_float(src);
    g_meta[pos] = m;
}

// ---------------- fused 3-type aggregation of xn (gather, atomic-free) ----------------
__global__ void gather0_kernel() {
    int lane = threadIdx.x & 31;
    int v    = blockIdx.x * 8 + (threadIdx.x >> 5);

    const float4* __restrict__ xn4 = (const float4*)g_xn;
    int beg = g_rowptr[v];
    int end = g_rowptr[v + 1];

    float4 a0 = make_float4(0.f, 0.f, 0.f, 0.f);
    float4 a1 = make_float4(0.f, 0.f, 0.f, 0.f);
    float4 a2 = make_float4(0.f, 0.f, 0.f, 0.f);

    int j = beg;
    for (; j + 1 < end; j += 2) {
        float4 mA = __ldg(&g_meta[j]);
        float4 mB = __ldg(&g_meta[j + 1]);
        float4 xA = xn4[__float_as_int(mA.w) * 32 + lane];
        float4 xB = xn4[__float_as_int(mB.w) * 32 + lane];
        a0.x = fmaf(mA.x, xA.x, a0.x); a0.y = fmaf(mA.x, xA.y, a0.y);
        a0.z = fmaf(mA.x, xA.z, a0.z); a0.w = fmaf(mA.x, xA.w, a0.w);
        a1.x = fmaf(mA.y, xA.x, a1.x); a1.y = fmaf(mA.y, xA.y, a1.y);
        a1.z = fmaf(mA.y, xA.z, a1.z); a1.w = fmaf(mA.y, xA.w, a1.w);
        a2.x = fmaf(mA.z, xA.x, a2.x); a2.y = fmaf(mA.z, xA.y, a2.y);
        a2.z = fmaf(mA.z, xA.z, a2.z); a2.w = fmaf(mA.z, xA.w, a2.w);
        a0.x = fmaf(mB.x, xB.x, a0.x); a0.y = fmaf(mB.x, xB.y, a0.y);
        a0.z = fmaf(mB.x, xB.z, a0.z); a0.w = fmaf(mB.x, xB.w, a0.w);
        a1.x = fmaf(mB.y, xB.x, a1.x); a1.y = fmaf(mB.y, xB.y, a1.y);
        a1.z = fmaf(mB.y, xB.z, a1.z); a1.w = fmaf(mB.y, xB.w, a1.w);
        a2.x = fmaf(mB.z, xB.x, a2.x); a2.y = fmaf(mB.z, xB.y, a2.y);
        a2.z = fmaf(mB.z, xB.z, a2.z); a2.w = fmaf(mB.z, xB.w, a2.w);
    }
    if (j < end) {
        float4 m = __ldg(&g_meta[j]);
        float4 x = xn4[__float_as_int(m.w) * 32 + lane];
        a0.x = fmaf(m.x, x.x, a0.x); a0.y = fmaf(m.x, x.y, a0.y);
        a0.z = fmaf(m.x, x.z, a0.z); a0.w = fmaf(m.x, x.w, a0.w);
        a1.x = fmaf(m.y, x.x, a1.x); a1.y = fmaf(m.y, x.y, a1.y);
        a1.z = fmaf(m.y, x.z, a1.z); a1.w = fmaf(m.y, x.w, a1.w);
        a2.x = fmaf(m.z, x.x, a2.x); a2.y = fmaf(m.z, x.y, a2.y);
        a2.z = fmaf(m.z, x.z, a2.z); a2.w = fmaf(m.z, x.w, a2.w);
    }

    float4 xv = xn4[v * 32 + lane];
    float i0 = g_dis[0 * N_NODES + v]; i0 *= i0;
    float i1 = g_dis[1 * N_NODES + v]; i1 *= i1;
    float i2 = g_dis[2 * N_NODES + v]; i2 *= i2;
    a0.x = fmaf(i0, xv.x, a0.x); a0.y = fmaf(i0, xv.y, a0.y);
    a0.z = fmaf(i0, xv.z, a0.z); a0.w = fmaf(i0, xv.w, a0.w);
    a1.x = fmaf(i1, xv.x, a1.x); a1.y = fmaf(i1, xv.y, a1.y);
    a1.z = fmaf(i1, xv.z, a1.z); a1.w = fmaf(i1, xv.w, a1.w);
    a2.x = fmaf(i2, xv.x, a2.x); a2.y = fmaf(i2, xv.y, a2.y);
    a2.z = fmaf(i2, xv.z, a2.z); a2.w = fmaf(i2, xv.w, a2.w);

    float4* o = (float4*)g_agg;
    o[(0 * N_NODES + v) * 32 + lane] = a0;
    o[(1 * N_NODES + v) * 32 + lane] = a1;
    o[(2 * N_NODES + v) * 32 + lane] = a2;
}

// ---------------- f32x2 GEMM: C[M,N] = A[M,K] @ W[K,N] (+bias, relu) ----------------
// BM=BN=128, BK=16, 256 threads, 8x8 microtile, 1 block/SM (full 256-reg budget,
// no accumulator spills), double-buffered smem (one sync per chunk).
__global__ void __launch_bounds__(256, 1) gemm_f32x2(
    const float* __restrict__ Abase, long long Astride,
    const float* __restrict__ Wbase, long long Wstride,
    float* __restrict__ Cbase, long long Cstride,
    const float* __restrict__ biasBase, int biasStride,
    int M, int N, int K, int doRelu)
{
    __shared__ float As[2][16][132];   // transposed A tile, +4 pad
    __shared__ float Bs[2][16][128];

    const int t   = blockIdx.z;
    const float* A = Abase + (long long)t * Astride;
    const float* W = Wbase + (long long)t * Wstride;
    float*       C = Cbase + (long long)t * Cstride;

    const int tid = threadIdx.x;
    const int tm  = (tid >> 4) * 8;
    const int tn  = (tid & 15) * 8;
    const int bm0 = blockIdx.y * 128;
    const int bn0 = blockIdx.x * 128;

    const int a_r = tid >> 2;           // 0..63 (rows a_r, a_r+64)
    const int a_k = (tid & 3) * 4;
    const int b_r = tid >> 5;           // 0..7 (rows b_r, b_r+8)
    const int b_c = (tid & 31) * 4;

    unsigned long long acc[8][4];
#pragma unroll
    for (int i = 0; i < 8; i++)
#pragma unroll
        for (int j = 0; j < 4; j++) acc[i][j] = 0ULL;

    float4 aReg[2], bReg[2];

    // prologue: chunk 0 -> stage 0
    aReg[0] = *(const float4*)(A + (long long)(bm0 + a_r)      * K + a_k);
    aReg[1] = *(const float4*)(A + (long long)(bm0 + a_r + 64) * K + a_k);
    bReg[0] = *(const float4*)(W + (long long)(b_r)     * N + bn0 + b_c);
    bReg[1] = *(const float4*)(W + (long long)(b_r + 8) * N + bn0 + b_c);

    As[0][a_k + 0][a_r] = aReg[0].x; As[0][a_k + 1][a_r] = aReg[0].y;
    As[0][a_k + 2][a_r] = aReg[0].z; As[0][a_k + 3][a_r] = aReg[0].w;
    As[0][a_k + 0][a_r + 64] = aReg[1].x; As[0][a_k + 1][a_r + 64] = aReg[1].y;
    As[0][a_k + 2][a_r + 64] = aReg[1].z; As[0][a_k + 3][a_r + 64] = aReg[1].w;
    *(float4*)&Bs[0][b_r][b_c]     = bReg[0];
    *(float4*)&Bs[0][b_r + 8][b_c] = bReg[1];
    __syncthreads();

    const int nchunks = K >> 4;
    int stage = 0;
    for (int c = 0; c < nchunks; c++) {
        bool more = (c + 1 < nchunks);
        if (more) {
            int k0 = (c + 1) << 4;
            aReg[0] = *(const float4*)(A + (long long)(bm0 + a_r)      * K + k0 + a_k);
            aReg[1] = *(const float4*)(A + (long long)(bm0 + a_r + 64) * K + k0 + a_k);
            bReg[0] = *(const float4*)(W + (long long)(k0 + b_r)     * N + bn0 + b_c);
            bReg[1] = *(const float4*)(W + (long long)(k0 + b_r + 8) * N + bn0 + b_c);
        }
#pragma unroll
        for (int k = 0; k < 16; k++) {
            float a[8];
            *(float4*)&a[0] = *(const float4*)&As[stage][k][tm];
            *(float4*)&a[4] = *(const float4*)&As[stage][k][tm + 4];
            ulonglong2 t0 = *(const ulonglong2*)&Bs[stage][k][tn];
            ulonglong2 t1 = *(const ulonglong2*)&Bs[stage][k][tn + 4];
            unsigned long long b[4] = {t0.x, t0.y, t1.x, t1.y};
#pragma unroll
            for (int i = 0; i < 8; i++) {
                unsigned long long ap = pack2(a[i]);
                ffma2(acc[i][0], ap, b[0]);
                ffma2(acc[i][1], ap, b[1]);
                ffma2(acc[i][2], ap, b[2]);
                ffma2(acc[i][3], ap, b[3]);
            }
        }
        if (more) {
            int ns = stage ^ 1;
            As[ns][a_k + 0][a_r] = aReg[0].x; As[ns][a_k + 1][a_r] = aReg[0].y;
            As[ns][a_k + 2][a_r] = aReg[0].z; As[ns][a_k + 3][a_r] = aReg[0].w;
            As[ns][a_k + 0][a_r + 64] = aReg[1].x; As[ns][a_k + 1][a_r + 64] = aReg[1].y;
            As[ns][a_k + 2][a_r + 64] = aReg[1].z; As[ns][a_k + 3][a_r + 64] = aReg[1].w;
            *(float4*)&Bs[ns][b_r][b_c]     = bReg[0];
            *(float4*)&Bs[ns][b_r + 8][b_c] = bReg[1];
            __syncthreads();
            stage = ns;
        }
    }

    float bias[8];
    if (biasBase) {
        const float* bp = biasBase + (long long)t * biasStride + bn0 + tn;
        *(float4*)&bias[0] = *(const float4*)(bp);
        *(float4*)&bias[4] = *(const float4*)(bp + 4);
    } else {
#pragma unroll
        for (int j = 0; j < 8; j++) bias[j] = 0.0f;
    }

#pragma unroll
    for (int i = 0; i < 8; i++) {
        float o[8];
#pragma unroll
        for (int j = 0; j < 4; j++) {
            float2 p = unpack2(acc[i][j]);
            o[2 * j]     = p.x + bias[2 * j];
            o[2 * j + 1] = p.y + bias[2 * j + 1];
        }
        if (doRelu) {
#pragma unroll
            for (int j = 0; j < 8; j++) o[j] = fmaxf(o[j], 0.0f);
        }
        float* cp = C + (long long)(bm0 + tm + i) * N + bn0 + tn;
        *(float4*)(cp)     = *(float4*)&o[0];
        *(float4*)(cp + 4) = *(float4*)&o[4];
    }
}

// ---------------- layer-2 gather: all 3 types fused, + output permutation ----------------
__global__ void gather2_kernel(const float* __restrict__ b2, float* __restrict__ out) {
    int lane = threadIdx.x & 31;
    int v    = blockIdx.x * 8 + (threadIdx.x >> 5);

    const float4* __restrict__ h2a = (const float4*)(g_h2);
    const float4* __restrict__ h2b = (const float4*)(g_h2 + (long long)N_NODES * D2);
    const float4* __restrict__ h2c = (const float4*)(g_h2 + 2LL * N_NODES * D2);
    int beg = g_rowptr[v];
    int end = g_rowptr[v + 1];

    float4 a0 = make_float4(0.f, 0.f, 0.f, 0.f);
    float4 a1 = make_float4(0.f, 0.f, 0.f, 0.f);
    float4 a2 = make_float4(0.f, 0.f, 0.f, 0.f);

    for (int j = beg; j < end; j++) {
        float4 m = __ldg(&g_meta[j]);
        int src = __float_as_int(m.w);
        float4 x0 = h2a[src * 32 + lane];
        float4 x1 = h2b[src * 32 + lane];
        float4 x2 = h2c[src * 32 + lane];
        a0.x = fmaf(m.x, x0.x, a0.x); a0.y = fmaf(m.x, x0.y, a0.y);
        a0.z = fmaf(m.x, x0.z, a0.z); a0.w = fmaf(m.x, x0.w, a0.w);
        a1.x = fmaf(m.y, x1.x, a1.x); a1.y = fmaf(m.y, x1.y, a1.y);
        a1.z = fmaf(m.y, x1.z, a1.z); a1.w = fmaf(m.y, x1.w, a1.w);
        a2.x = fmaf(m.z, x2.x, a2.x); a2.y = fmaf(m.z, x2.y, a2.y);
        a2.z = fmaf(m.z, x2.z, a2.z); a2.w = fmaf(m.z, x2.w, a2.w);
    }

    float i0 = g_dis[0 * N_NODES + v]; i0 *= i0;
    float i1 = g_dis[1 * N_NODES + v]; i1 *= i1;
    float i2 = g_dis[2 * N_NODES + v]; i2 *= i2;
    float4 s0 = h2a[v * 32 + lane];
    float4 s1 = h2b[v * 32 + lane];
    float4 s2 = h2c[v * 32 + lane];
    float4 bb0 = ((const float4*)(b2 + 0 * D2))[lane];
    float4 bb1 = ((const float4*)(b2 + 1 * D2))[lane];
    float4 bb2 = ((const float4*)(b2 + 2 * D2))[lane];

    a0.x = fmaxf(fmaf(i0, s0.x, a0.x) + bb0.x, 0.f);
    a0.y = fmaxf(fmaf(i0, s0.y, a0.y) + bb0.y, 0.f);
    a0.z = fmaxf(fmaf(i0, s0.z, a0.z) + bb0.z, 0.f);
    a0.w = fmaxf(fmaf(i0, s0.w, a0.w) + bb0.w, 0.f);
    a1.x = fmaxf(fmaf(i1, s1.x, a1.x) + bb1.x, 0.f);
    a1.y = fmaxf(fmaf(i1, s1.y, a1.y) + bb1.y, 0.f);
    a1.z = fmaxf(fmaf(i1, s1.z, a1.z) + bb1.z, 0.f);
    a1.w = fmaxf(fmaf(i1, s1.w, a1.w) + bb1.w, 0.f);
    a2.x = fmaxf(fmaf(i2, s2.x, a2.x) + bb2.x, 0.f);
    a2.y = fmaxf(fmaf(i2, s2.y, a2.y) + bb2.y, 0.f);
    a2.z = fmaxf(fmaf(i2, s2.z, a2.z) + bb2.z, 0.f);
    a2.w = fmaxf(fmaf(i2, s2.w, a2.w) + bb2.w, 0.f);

    int bt = v >> 13;
    int sq = (v >> 9) & 15;
    int vv = v & 511;
    int orow = bt * NNG + vv;
    long long base = ((long long)(orow * SEQ + sq)) * (NT * D2) + lane * 4;
    *(float4*)(out + base)          = a0;
    *(float4*)(out + base + D2)     = a1;
    *(float4*)(out + base + 2 * D2) = a2;
}

// ---------------- launch ----------------
extern "C" void kernel_launch(void* const* d_in, const int* in_sizes, int n_in,
                              void* d_out, int out_size) {
    const float* x  = (const float*)d_in[0];
    const float* ea = (const float*)d_in[1];
    const float* W1 = (const float*)d_in[2];
    const float* b1 = (const float*)d_in[3];
    const float* W2 = (const float*)d_in[4];
    const float* b2 = (const float*)d_in[5];
    const int*   ei = (const int*)d_in[6];
    float* out = (float*)d_out;

    float *agg, *h1r, *h2;
    cudaGetSymbolAddress((void**)&agg, g_agg);
    cudaGetSymbolAddress((void**)&h1r, g_h1r);
    cudaGetSymbolAddress((void**)&h2,  g_h2);

    zero_kernel     <<<384, 256>>>();
    stats_kernel    <<<128, 128>>>(x);
    finstats_kernel <<<1, 128>>>();
    normalize_kernel<<<4096, 256>>>(x);
    hist_kernel     <<<E_EDGES / 256, 256>>>(ei, ea);
    scan_kernel     <<<1, 1024>>>();
    dis_kernel      <<<384, 256>>>();
    fill_kernel     <<<E_EDGES / 256, 256>>>(ei, ea);
    gather0_kernel  <<<N_NODES / 8, 256>>>();

    // h1r_t = relu(agg_t @ W1_t + b1_t)   [32768,128]@[128,256], all 3 types in z
    gemm_f32x2<<<dim3(D1 / 128, N_NODES / 128, NT), 256>>>(
        agg, (long long)N_NODES * F_IN, W1, (long long)F_IN * D1,
        h1r, (long long)N_NODES * D1, b1, D1,
        N_NODES, D1, F_IN, 1);

    // h2_t = h1r_t @ W2_t   [32768,256]@[256,128]
    gemm_f32x2<<<dim3(D2 / 128, N_NODES / 128, NT), 256>>>(
        h1r, (long long)N_NODES * D1, W2, (long long)D1 * D2,
        h2, (long long)N_NODES * D2, (const float*)nullptr, 0,
        N_NODES, D2, D1, 0);

    gather2_kernel<<<N_NODES / 8, 256>>>(b2, out);
}

// round 6
// speedup vs baseline: 1.6689x; 1.5658x over previous
#include <cuda_runtime.h>
#include <math.h>
#include <stdint.h>

// Problem constants (fixed by setup_inputs)
#define N_NODES 32768
#define E_EDGES 524288
#define F_IN    128
#define D1      256
#define D2      128
#define NT      3
#define SEQ     16
#define NNG     512

// ---------------- scratch (device globals; no allocation allowed) ----------------
__device__ float  g_xn  [N_NODES * F_IN];
__device__ float  g_agg [NT * N_NODES * F_IN];
__device__ float  g_h1r [NT * N_NODES * D1];
__device__ float  g_h2  [NT * N_NODES * D2];
__device__ float  g_deg [NT * N_NODES];
__device__ float  g_dis [NT * N_NODES];
__device__ int    g_counts[N_NODES];
__device__ int    g_rowptr[N_NODES + 1];
__device__ int    g_cursor[N_NODES];
__device__ float4 g_meta[E_EDGES];                   // {w0,w1,w2,src-as-float} CSR by dst
__device__ float  g_colsum[F_IN];
__device__ float  g_colsq [F_IN];
__device__ float  g_mean[F_IN];
__device__ float  g_rstd[F_IN];

// ---------------- helpers ----------------
__device__ __forceinline__ uint32_t f2tf32(float f) {
    uint32_t r;
    asm("cvt.rna.tf32.f32 %0, %1;" : "=r"(r) : "f"(f));
    return r;
}
__device__ __forceinline__ void mma_tf32(float* c,
    uint32_t a0, uint32_t a1, uint32_t a2, uint32_t a3,
    uint32_t b0, uint32_t b1)
{
    asm volatile(
        "mma.sync.aligned.m16n8k8.row.col.f32.tf32.tf32.f32 "
        "{%0,%1,%2,%3}, {%4,%5,%6,%7}, {%8,%9}, {%0,%1,%2,%3};"
        : "+f"(c[0]), "+f"(c[1]), "+f"(c[2]), "+f"(c[3])
        : "r"(a0), "r"(a1), "r"(a2), "r"(a3), "r"(b0), "r"(b1));
}

// ---------------- small prep kernels ----------------
__global__ void zero_kernel() {
    int i = blockIdx.x * 256 + threadIdx.x;
    if (i < N_NODES)      g_counts[i] = 0;
    if (i < NT * N_NODES) g_deg[i] = 0.0f;
    if (i < F_IN) { g_colsum[i] = 0.0f; g_colsq[i] = 0.0f; }
}

__global__ void stats_kernel(const float* __restrict__ x) {
    int c  = threadIdx.x;
    int r0 = blockIdx.x * 256;
    float s = 0.0f, q = 0.0f;
    for (int r = 0; r < 256; r++) {
        float v = x[(r0 + r) * F_IN + c];
        s += v; q += v * v;
    }
    atomicAdd(&g_colsum[c], s);
    atomicAdd(&g_colsq[c],  q);
}

__global__ void finstats_kernel() {
    int c = threadIdx.x;
    float n = (float)N_NODES;
    float mean = g_colsum[c] / n;
    float var  = (g_colsq[c] - n * mean * mean) / (n - 1.0f);  // ddof=1
    g_mean[c] = mean;
    g_rstd[c] = rsqrtf(var);
}

__global__ void normalize_kernel(const float* __restrict__ x) {
    int i  = blockIdx.x * 256 + threadIdx.x;
    int c4 = (i & 31) * 4;
    float4 v = ((const float4*)x)[i];
    v.x = (v.x - g_mean[c4 + 0]) * g_rstd[c4 + 0];
    v.y = (v.y - g_mean[c4 + 1]) * g_rstd[c4 + 1];
    v.z = (v.z - g_mean[c4 + 2]) * g_rstd[c4 + 2];
    v.w = (v.w - g_mean[c4 + 3]) * g_rstd[c4 + 3];
    ((float4*)g_xn)[i] = v;
}

__global__ void hist_kernel(const int* __restrict__ ei, const float* __restrict__ ea) {
    int e = blockIdx.x * 256 + threadIdx.x;
    if (e >= E_EDGES) return;
    int dst = ei[E_EDGES + e];
    atomicAdd(&g_counts[dst], 1);
    atomicAdd(&g_deg[0 * N_NODES + dst], fabsf(ea[3 * e + 0]));
    atomicAdd(&g_deg[1 * N_NODES + dst], fabsf(ea[3 * e + 1]));
    atomicAdd(&g_deg[2 * N_NODES + dst], fabsf(ea[3 * e + 2]));
}

__global__ void scan_kernel() {
    __shared__ int sums[1024];
    int tid  = threadIdx.x;
    int base = tid * 32;
    int vals[32];
    int s = 0;
#pragma unroll
    for (int i = 0; i < 32; i++) { int v = g_counts[base + i]; vals[i] = s; s += v; }
    sums[tid] = s;
    __syncthreads();
    for (int off = 1; off < 1024; off <<= 1) {
        int v = (tid >= off) ? sums[tid - off] : 0;
        __syncthreads();
        sums[tid] += v;
        __syncthreads();
    }
    int ex = (tid > 0) ? sums[tid - 1] : 0;
#pragma unroll
    for (int i = 0; i < 32; i++) {
        int p = ex + vals[i];
        g_rowptr[base + i] = p;
        g_cursor[base + i] = p;
    }
    if (tid == 1023) g_rowptr[N_NODES] = sums[1023];
}

__global__ void dis_kernel() {
    int i = blockIdx.x * 256 + threadIdx.x;
    if (i < NT * N_NODES) g_dis[i] = rsqrtf(g_deg[i] + 1.0f);
}

__global__ void fill_kernel(const int* __restrict__ ei, const float* __restrict__ ea) {
    int e = blockIdx.x * 256 + threadIdx.x;
    if (e >= E_EDGES) return;
    int src = ei[e];
    int dst = ei[E_EDGES + e];
    int pos = atomicAdd(&g_cursor[dst], 1);
    float4 m;
    m.x = g_dis[0 * N_NODES + src] * fabsf(ea[3 * e + 0]) * g_dis[0 * N_NODES + dst];
    m.y = g_dis[1 * N_NODES + src] * fabsf(ea[3 * e + 1]) * g_dis[1 * N_NODES + dst];
    m.z = g_dis[2 * N_NODES + src] * fabsf(ea[3 * e + 2]) * g_dis[2 * N_NODES + dst];
    m.w = __int_as_float(src);
    g_meta[pos] = m;
}

// ---------------- fused 3-type aggregation of xn (gather, atomic-free) ----------------
__global__ void gather0_kernel() {
    int lane = threadIdx.x & 31;
    int v    = blockIdx.x * 8 + (threadIdx.x >> 5);

    const float4* __restrict__ xn4 = (const float4*)g_xn;
    int beg = g_rowptr[v];
    int end = g_rowptr[v + 1];

    float4 a0 = make_float4(0.f, 0.f, 0.f, 0.f);
    float4 a1 = make_float4(0.f, 0.f, 0.f, 0.f);
    float4 a2 = make_float4(0.f, 0.f, 0.f, 0.f);

    int j = beg;
    for (; j + 1 < end; j += 2) {
        float4 mA = __ldg(&g_meta[j]);
        float4 mB = __ldg(&g_meta[j + 1]);
        float4 xA = xn4[__float_as_int(mA.w) * 32 + lane];
        float4 xB = xn4[__float_as_int(mB.w) * 32 + lane];
        a0.x = fmaf(mA.x, xA.x, a0.x); a0.y = fmaf(mA.x, xA.y, a0.y);
        a0.z = fmaf(mA.x, xA.z, a0.z); a0.w = fmaf(mA.x, xA.w, a0.w);
        a1.x = fmaf(mA.y, xA.x, a1.x); a1.y = fmaf(mA.y, xA.y, a1.y);
        a1.z = fmaf(mA.y, xA.z, a1.z); a1.w = fmaf(mA.y, xA.w, a1.w);
        a2.x = fmaf(mA.z, xA.x, a2.x); a2.y = fmaf(mA.z, xA.y, a2.y);
        a2.z = fmaf(mA.z, xA.z, a2.z); a2.w = fmaf(mA.z, xA.w, a2.w);
        a0.x = fmaf(mB.x, xB.x, a0.x); a0.y = fmaf(mB.x, xB.y, a0.y);
        a0.z = fmaf(mB.x, xB.z, a0.z); a0.w = fmaf(mB.x, xB.w, a0.w);
        a1.x = fmaf(mB.y, xB.x, a1.x); a1.y = fmaf(mB.y, xB.y, a1.y);
        a1.z = fmaf(mB.y, xB.z, a1.z); a1.w = fmaf(mB.y, xB.w, a1.w);
        a2.x = fmaf(mB.z, xB.x, a2.x); a2.y = fmaf(mB.z, xB.y, a2.y);
        a2.z = fmaf(mB.z, xB.z, a2.z); a2.w = fmaf(mB.z, xB.w, a2.w);
    }
    if (j < end) {
        float4 m = __ldg(&g_meta[j]);
        float4 x = xn4[__float_as_int(m.w) * 32 + lane];
        a0.x = fmaf(m.x, x.x, a0.x); a0.y = fmaf(m.x, x.y, a0.y);
        a0.z = fmaf(m.x, x.z, a0.z); a0.w = fmaf(m.x, x.w, a0.w);
        a1.x = fmaf(m.y, x.x, a1.x); a1.y = fmaf(m.y, x.y, a1.y);
        a1.z = fmaf(m.y, x.z, a1.z); a1.w = fmaf(m.y, x.w, a1.w);
        a2.x = fmaf(m.z, x.x, a2.x); a2.y = fmaf(m.z, x.y, a2.y);
        a2.z = fmaf(m.z, x.z, a2.z); a2.w = fmaf(m.z, x.w, a2.w);
    }

    float4 xv = xn4[v * 32 + lane];
    float i0 = g_dis[0 * N_NODES + v]; i0 *= i0;
    float i1 = g_dis[1 * N_NODES + v]; i1 *= i1;
    float i2 = g_dis[2 * N_NODES + v]; i2 *= i2;
    a0.x = fmaf(i0, xv.x, a0.x); a0.y = fmaf(i0, xv.y, a0.y);
    a0.z = fmaf(i0, xv.z, a0.z); a0.w = fmaf(i0, xv.w, a0.w);
    a1.x = fmaf(i1, xv.x, a1.x); a1.y = fmaf(i1, xv.y, a1.y);
    a1.z = fmaf(i1, xv.z, a1.z); a1.w = fmaf(i1, xv.w, a1.w);
    a2.x = fmaf(i2, xv.x, a2.x); a2.y = fmaf(i2, xv.y, a2.y);
    a2.z = fmaf(i2, xv.z, a2.z); a2.w = fmaf(i2, xv.w, a2.w);

    float4* o = (float4*)g_agg;
    o[(0 * N_NODES + v) * 32 + lane] = a0;
    o[(1 * N_NODES + v) * 32 + lane] = a1;
    o[(2 * N_NODES + v) * 32 + lane] = a2;
}

// ---------------- tf32 mma.sync GEMM: C[M,N] = A[M,K] @ W[K,N] (+bias, relu) ----------------
// Block 128x128, 256 threads = 8 warps (2 x 4), warp tile 64x32, K chunked by 32.
// Fragment layouts per PTX m16n8k8 tf32 (gid = lane>>2, tig = lane&3).
__global__ void __launch_bounds__(256) gemm_mma(
    const float* __restrict__ Abase, long long Astride,
    const float* __restrict__ Wbase, long long Wstride,
    float* __restrict__ Cbase, long long Cstride,
    const float* __restrict__ biasBase, int biasStride,
    int M, int N, int K, int doRelu)
{
    __shared__ uint32_t As[128][36];   // [m][k], pad->conflict-free frag reads, 16B-aligned rows
    __shared__ uint32_t Bs[32][136];   // [k][n], pad 8 -> conflict-free b-frag reads

    const int t   = blockIdx.z;
    const float* A = Abase + (long long)t * Astride;
    const float* W = Wbase + (long long)t * Wstride;
    float*       C = Cbase + (long long)t * Cstride;

    const int tid  = threadIdx.x;
    const int wid  = tid >> 5;
    const int lane = tid & 31;
    const int gid  = lane >> 2;
    const int tig  = lane & 3;
    const int wm0  = (wid & 1) * 64;
    const int wn0  = (wid >> 1) * 32;
    const int bm0  = blockIdx.y * 128;
    const int bn0  = blockIdx.x * 128;

    float acc[4][4][4];
#pragma unroll
    for (int i = 0; i < 4; i++)
#pragma unroll
        for (int j = 0; j < 4; j++)
#pragma unroll
            for (int q = 0; q < 4; q++) acc[i][j][q] = 0.0f;

    const int nch = K >> 5;
    for (int c = 0; c < nch; c++) {
        // A tile: 128 x 32 floats -> tf32
#pragma unroll
        for (int it = 0; it < 4; it++) {
            int idx = tid + it * 256;
            int r = idx >> 3, c4 = idx & 7;
            float4 v = *(const float4*)(A + (long long)(bm0 + r) * K + (c << 5) + c4 * 4);
            uint4 o = make_uint4(f2tf32(v.x), f2tf32(v.y), f2tf32(v.z), f2tf32(v.w));
            *(uint4*)&As[r][c4 * 4] = o;
        }
        // B tile: 32 x 128 floats -> tf32
#pragma unroll
        for (int it = 0; it < 4; it++) {
            int idx = tid + it * 256;
            int k = idx >> 5, n4 = idx & 31;
            float4 v = *(const float4*)(W + (long long)((c << 5) + k) * N + bn0 + n4 * 4);
            uint4 o = make_uint4(f2tf32(v.x), f2tf32(v.y), f2tf32(v.z), f2tf32(v.w));
            *(uint4*)&Bs[k][n4 * 4] = o;
        }
        __syncthreads();

#pragma unroll
        for (int ks = 0; ks < 4; ks++) {
            int kk = ks * 8;
            uint32_t bf[4][2];
#pragma unroll
            for (int nf = 0; nf < 4; nf++) {
                bf[nf][0] = Bs[kk + tig][wn0 + nf * 8 + gid];
                bf[nf][1] = Bs[kk + tig + 4][wn0 + nf * 8 + gid];
            }
#pragma unroll
            for (int mf = 0; mf < 4; mf++) {
                int r = wm0 + mf * 16 + gid;
                uint32_t a0 = As[r][kk + tig];
                uint32_t a1 = As[r + 8][kk + tig];
                uint32_t a2 = As[r][kk + tig + 4];
                uint32_t a3 = As[r + 8][kk + tig + 4];
#pragma unroll
                for (int nf = 0; nf < 4; nf++)
                    mma_tf32(acc[mf][nf], a0, a1, a2, a3, bf[nf][0], bf[nf][1]);
            }
        }
        __syncthreads();
    }

    // epilogue: bias + relu, float2 stores from C fragments
#pragma unroll
    for (int mf = 0; mf < 4; mf++) {
        int row = bm0 + wm0 + mf * 16 + gid;
#pragma unroll
        for (int nf = 0; nf < 4; nf++) {
            int col = bn0 + wn0 + nf * 8 + tig * 2;
            float b0 = 0.0f, b1 = 0.0f;
            if (biasBase) {
                const float* bp = biasBase + (long long)t * biasStride + col;
                b0 = bp[0]; b1 = bp[1];
            }
            float o0 = acc[mf][nf][0] + b0;
            float o1 = acc[mf][nf][1] + b1;
            float o2 = acc[mf][nf][2] + b0;
            float o3 = acc[mf][nf][3] + b1;
            if (doRelu) {
                o0 = fmaxf(o0, 0.f); o1 = fmaxf(o1, 0.f);
                o2 = fmaxf(o2, 0.f); o3 = fmaxf(o3, 0.f);
            }
            *(float2*)(C + (long long)row * N + col)       = make_float2(o0, o1);
            *(float2*)(C + (long long)(row + 8) * N + col) = make_float2(o2, o3);
        }
    }
}

// ---------------- layer-2 gather: all 3 types fused, + output permutation ----------------
__global__ void gather2_kernel(const float* __restrict__ b2, float* __restrict__ out) {
    int lane = threadIdx.x & 31;
    int v    = blockIdx.x * 8 + (threadIdx.x >> 5);

    const float4* __restrict__ h2a = (const float4*)(g_h2);
    const float4* __restrict__ h2b = (const float4*)(g_h2 + (long long)N_NODES * D2);
    const float4* __restrict__ h2c = (const float4*)(g_h2 + 2LL * N_NODES * D2);
    int beg = g_rowptr[v];
    int end = g_rowptr[v + 1];

    float4 a0 = make_float4(0.f, 0.f, 0.f, 0.f);
    float4 a1 = make_float4(0.f, 0.f, 0.f, 0.f);
    float4 a2 = make_float4(0.f, 0.f, 0.f, 0.f);

    for (int j = beg; j < end; j++) {
        float4 m = __ldg(&g_meta[j]);
        int src = __float_as_int(m.w);
        float4 x0 = h2a[src * 32 + lane];
        float4 x1 = h2b[src * 32 + lane];
        float4 x2 = h2c[src * 32 + lane];
        a0.x = fmaf(m.x, x0.x, a0.x); a0.y = fmaf(m.x, x0.y, a0.y);
        a0.z = fmaf(m.x, x0.z, a0.z); a0.w = fmaf(m.x, x0.w, a0.w);
        a1.x = fmaf(m.y, x1.x, a1.x); a1.y = fmaf(m.y, x1.y, a1.y);
        a1.z = fmaf(m.y, x1.z, a1.z); a1.w = fmaf(m.y, x1.w, a1.w);
        a2.x = fmaf(m.z, x2.x, a2.x); a2.y = fmaf(m.z, x2.y, a2.y);
        a2.z = fmaf(m.z, x2.z, a2.z); a2.w = fmaf(m.z, x2.w, a2.w);
    }

    float i0 = g_dis[0 * N_NODES + v]; i0 *= i0;
    float i1 = g_dis[1 * N_NODES + v]; i1 *= i1;
    float i2 = g_dis[2 * N_NODES + v]; i2 *= i2;
    float4 s0 = h2a[v * 32 + lane];
    float4 s1 = h2b[v * 32 + lane];
    float4 s2 = h2c[v * 32 + lane];
    float4 bb0 = ((const float4*)(b2 + 0 * D2))[lane];
    float4 bb1 = ((const float4*)(b2 + 1 * D2))[lane];
    float4 bb2 = ((const float4*)(b2 + 2 * D2))[lane];

    a0.x = fmaxf(fmaf(i0, s0.x, a0.x) + bb0.x, 0.f);
    a0.y = fmaxf(fmaf(i0, s0.y, a0.y) + bb0.y, 0.f);
    a0.z = fmaxf(fmaf(i0, s0.z, a0.z) + bb0.z, 0.f);
    a0.w = fmaxf(fmaf(i0, s0.w, a0.w) + bb0.w, 0.f);
    a1.x = fmaxf(fmaf(i1, s1.x, a1.x) + bb1.x, 0.f);
    a1.y = fmaxf(fmaf(i1, s1.y, a1.y) + bb1.y, 0.f);
    a1.z = fmaxf(fmaf(i1, s1.z, a1.z) + bb1.z, 0.f);
    a1.w = fmaxf(fmaf(i1, s1.w, a1.w) + bb1.w, 0.f);
    a2.x = fmaxf(fmaf(i2, s2.x, a2.x) + bb2.x, 0.f);
    a2.y = fmaxf(fmaf(i2, s2.y, a2.y) + bb2.y, 0.f);
    a2.z = fmaxf(fmaf(i2, s2.z, a2.z) + bb2.z, 0.f);
    a2.w = fmaxf(fmaf(i2, s2.w, a2.w) + bb2.w, 0.f);

    int bt = v >> 13;
    int sq = (v >> 9) & 15;
    int vv = v & 511;
    int orow = bt * NNG + vv;
    long long base = ((long long)(orow * SEQ + sq)) * (NT * D2) + lane * 4;
    *(float4*)(out + base)          = a0;
    *(float4*)(out + base + D2)     = a1;
    *(float4*)(out + base + 2 * D2) = a2;
}

// ---------------- launch ----------------
extern "C" void kernel_launch(void* const* d_in, const int* in_sizes, int n_in,
                              void* d_out, int out_size) {
    const float* x  = (const float*)d_in[0];
    const float* ea = (const float*)d_in[1];
    const float* W1 = (const float*)d_in[2];
    const float* b1 = (const float*)d_in[3];
    const float* W2 = (const float*)d_in[4];
    const float* b2 = (const float*)d_in[5];
    const int*   ei = (const int*)d_in[6];
    float* out = (float*)d_out;

    float *agg, *h1r, *h2;
    cudaGetSymbolAddress((void**)&agg, g_agg);
    cudaGetSymbolAddress((void**)&h1r, g_h1r);
    cudaGetSymbolAddress((void**)&h2,  g_h2);

    zero_kernel     <<<384, 256>>>();
    stats_kernel    <<<128, 128>>>(x);
    finstats_kernel <<<1, 128>>>();
    normalize_kernel<<<4096, 256>>>(x);
    hist_kernel     <<<E_EDGES / 256, 256>>>(ei, ea);
    scan_kernel     <<<1, 1024>>>();
    dis_kernel      <<<384, 256>>>();
    fill_kernel     <<<E_EDGES / 256, 256>>>(ei, ea);
    gather0_kernel  <<<N_NODES / 8, 256>>>();

    // h1r_t = relu(agg_t @ W1_t + b1_t)   [32768,128]@[128,256]
    gemm_mma<<<dim3(D1 / 128, N_NODES / 128, NT), 256>>>(
        agg, (long long)N_NODES * F_IN, W1, (long long)F_IN * D1,
        h1r, (long long)N_NODES * D1, b1, D1,
        N_NODES, D1, F_IN, 1);

    // h2_t = h1r_t @ W2_t   [32768,256]@[256,128]
    gemm_mma<<<dim3(D2 / 128, N_NODES / 128, NT), 256>>>(
        h1r, (long long)N_NODES * D1, W2, (long long)D1 * D2,
        h2, (long long)N_NODES * D2, (const float*)nullptr, 0,
        N_NODES, D2, D1, 0);

    gather2_kernel<<<N_NODES / 8, 256>>>(b2, out);
}

// round 7
// speedup vs baseline: 1.8301x; 1.0966x over previous
#include <cuda_runtime.h>
#include <cuda_fp16.h>
#include <math.h>
#include <stdint.h>

// Problem constants (fixed by setup_inputs)
#define N_NODES 32768
#define E_EDGES 524288
#define F_IN    128
#define D1      256
#define D2      128
#define NT      3
#define SEQ     16
#define NNG     512

// ---------------- scratch (device globals; no allocation allowed) ----------------
__device__ float  g_agg [NT * N_NODES * F_IN];       // 48 MB aggregated normalized x
__device__ __half g_h1r [NT * N_NODES * D1];         // 48 MB relu(agg@W1+b1), fp16
__device__ __half g_h2  [NT * N_NODES * D2];         // 24 MB h1r@W2, fp16
__device__ float  g_deg [NT * N_NODES];
__device__ float  g_dis [NT * N_NODES];
__device__ int    g_counts[N_NODES];
__device__ int    g_rowptr[N_NODES + 1];
__device__ int    g_cursor[N_NODES];
__device__ float4 g_meta[E_EDGES];                   // {w0,w1,w2,src-as-float} CSR by dst
__device__ float  g_colsum[F_IN];
__device__ float  g_colsq [F_IN];
__device__ float  g_mean[F_IN];
__device__ float  g_rstd[F_IN];

// ---------------- helpers ----------------
__device__ __forceinline__ uint32_t f2tf32(float f) {
    uint32_t r;
    asm("cvt.rna.tf32.f32 %0, %1;" : "=r"(r) : "f"(f));
    return r;
}
__device__ __forceinline__ void mma_tf32(float* c,
    uint32_t a0, uint32_t a1, uint32_t a2, uint32_t a3,
    uint32_t b0, uint32_t b1)
{
    asm volatile(
        "mma.sync.aligned.m16n8k8.row.col.f32.tf32.tf32.f32 "
        "{%0,%1,%2,%3}, {%4,%5,%6,%7}, {%8,%9}, {%0,%1,%2,%3};"
        : "+f"(c[0]), "+f"(c[1]), "+f"(c[2]), "+f"(c[3])
        : "r"(a0), "r"(a1), "r"(a2), "r"(a3), "r"(b0), "r"(b1));
}

// ---------------- small prep kernels ----------------
__global__ void zero_kernel() {
    int i = blockIdx.x * 256 + threadIdx.x;
    if (i < N_NODES)      g_counts[i] = 0;
    if (i < NT * N_NODES) g_deg[i] = 0.0f;
    if (i < F_IN) { g_colsum[i] = 0.0f; g_colsq[i] = 0.0f; }
}

__global__ void stats_kernel(const float* __restrict__ x) {
    int c  = threadIdx.x;
    int r0 = blockIdx.x * 256;
    float s = 0.0f, q = 0.0f;
    for (int r = 0; r < 256; r++) {
        float v = x[(r0 + r) * F_IN + c];
        s += v; q += v * v;
    }
    atomicAdd(&g_colsum[c], s);
    atomicAdd(&g_colsq[c],  q);
}

__global__ void finstats_kernel() {
    int c = threadIdx.x;
    float n = (float)N_NODES;
    float mean = g_colsum[c] / n;
    float var  = (g_colsq[c] - n * mean * mean) / (n - 1.0f);  // ddof=1
    g_mean[c] = mean;
    g_rstd[c] = rsqrtf(var);
}

__global__ void hist_kernel(const int* __restrict__ ei, const float* __restrict__ ea) {
    int e = blockIdx.x * 256 + threadIdx.x;
    if (e >= E_EDGES) return;
    int dst = ei[E_EDGES + e];
    atomicAdd(&g_counts[dst], 1);
    atomicAdd(&g_deg[0 * N_NODES + dst], fabsf(ea[3 * e + 0]));
    atomicAdd(&g_deg[1 * N_NODES + dst], fabsf(ea[3 * e + 1]));
    atomicAdd(&g_deg[2 * N_NODES + dst], fabsf(ea[3 * e + 2]));
}

__global__ void scan_kernel() {
    __shared__ int sums[1024];
    int tid  = threadIdx.x;
    int base = tid * 32;
    int vals[32];
    int s = 0;
#pragma unroll
    for (int i = 0; i < 32; i++) { int v = g_counts[base + i]; vals[i] = s; s += v; }
    sums[tid] = s;
    __syncthreads();
    for (int off = 1; off < 1024; off <<= 1) {
        int v = (tid >= off) ? sums[tid - off] : 0;
        __syncthreads();
        sums[tid] += v;
        __syncthreads();
    }
    int ex = (tid > 0) ? sums[tid - 1] : 0;
#pragma unroll
    for (int i = 0; i < 32; i++) {
        int p = ex + vals[i];
        g_rowptr[base + i] = p;
        g_cursor[base + i] = p;
    }
    if (tid == 1023) g_rowptr[N_NODES] = sums[1023];
}

__global__ void dis_kernel() {
    int i = blockIdx.x * 256 + threadIdx.x;
    if (i < NT * N_NODES) g_dis[i] = rsqrtf(g_deg[i] + 1.0f);
}

__global__ void fill_kernel(const int* __restrict__ ei, const float* __restrict__ ea) {
    int e = blockIdx.x * 256 + threadIdx.x;
    if (e >= E_EDGES) return;
    int src = ei[e];
    int dst = ei[E_EDGES + e];
    int pos = atomicAdd(&g_cursor[dst], 1);
    float4 m;
    m.x = g_dis[0 * N_NODES + src] * fabsf(ea[3 * e + 0]) * g_dis[0 * N_NODES + dst];
    m.y = g_dis[1 * N_NODES + src] * fabsf(ea[3 * e + 1]) * g_dis[1 * N_NODES + dst];
    m.z = g_dis[2 * N_NODES + src] * fabsf(ea[3 * e + 2]) * g_dis[2 * N_NODES + dst];
    m.w = __int_as_float(src);
    g_meta[pos] = m;
}

// ---------------- fused normalization + 3-type aggregation (gather, atomic-free) ----------------
__global__ void gather0_kernel(const float* __restrict__ x) {
    int lane = threadIdx.x & 31;
    int v    = blockIdx.x * 8 + (threadIdx.x >> 5);

    const float4* __restrict__ x4 = (const float4*)x;
    float4 mu = ((const float4*)g_mean)[lane];
    float4 rs = ((const float4*)g_rstd)[lane];

    int beg = g_rowptr[v];
    int end = g_rowptr[v + 1];

    float4 a0 = make_float4(0.f, 0.f, 0.f, 0.f);
    float4 a1 = make_float4(0.f, 0.f, 0.f, 0.f);
    float4 a2 = make_float4(0.f, 0.f, 0.f, 0.f);

    int j = beg;
    for (; j + 1 < end; j += 2) {
        float4 mA = __ldg(&g_meta[j]);
        float4 mB = __ldg(&g_meta[j + 1]);
        float4 xA = x4[__float_as_int(mA.w) * 32 + lane];
        float4 xB = x4[__float_as_int(mB.w) * 32 + lane];
        xA.x = (xA.x - mu.x) * rs.x; xA.y = (xA.y - mu.y) * rs.y;
        xA.z = (xA.z - mu.z) * rs.z; xA.w = (xA.w - mu.w) * rs.w;
        xB.x = (xB.x - mu.x) * rs.x; xB.y = (xB.y - mu.y) * rs.y;
        xB.z = (xB.z - mu.z) * rs.z; xB.w = (xB.w - mu.w) * rs.w;
        a0.x = fmaf(mA.x, xA.x, a0.x); a0.y = fmaf(mA.x, xA.y, a0.y);
        a0.z = fmaf(mA.x, xA.z, a0.z); a0.w = fmaf(mA.x, xA.w, a0.w);
        a1.x = fmaf(mA.y, xA.x, a1.x); a1.y = fmaf(mA.y, xA.y, a1.y);
        a1.z = fmaf(mA.y, xA.z, a1.z); a1.w = fmaf(mA.y, xA.w, a1.w);
        a2.x = fmaf(mA.z, xA.x, a2.x); a2.y = fmaf(mA.z, xA.y, a2.y);
        a2.z = fmaf(mA.z, xA.z, a2.z); a2.w = fmaf(mA.z, xA.w, a2.w);
        a0.x = fmaf(mB.x, xB.x, a0.x); a0.y = fmaf(mB.x, xB.y, a0.y);
        a0.z = fmaf(mB.x, xB.z, a0.z); a0.w = fmaf(mB.x, xB.w, a0.w);
        a1.x = fmaf(mB.y, xB.x, a1.x); a1.y = fmaf(mB.y, xB.y, a1.y);
        a1.z = fmaf(mB.y, xB.z, a1.z); a1.w = fmaf(mB.y, xB.w, a1.w);
        a2.x = fmaf(mB.z, xB.x, a2.x); a2.y = fmaf(mB.z, xB.y, a2.y);
        a2.z = fmaf(mB.z, xB.z, a2.z); a2.w = fmaf(mB.z, xB.w, a2.w);
    }
    if (j < end) {
        float4 m = __ldg(&g_meta[j]);
        float4 xv = x4[__float_as_int(m.w) * 32 + lane];
        xv.x = (xv.x - mu.x) * rs.x; xv.y = (xv.y - mu.y) * rs.y;
        xv.z = (xv.z - mu.z) * rs.z; xv.w = (xv.w - mu.w) * rs.w;
        a0.x = fmaf(m.x, xv.x, a0.x); a0.y = fmaf(m.x, xv.y, a0.y);
        a0.z = fmaf(m.x, xv.z, a0.z); a0.w = fmaf(m.x, xv.w, a0.w);
        a1.x = fmaf(m.y, xv.x, a1.x); a1.y = fmaf(m.y, xv.y, a1.y);
        a1.z = fmaf(m.y, xv.z, a1.z); a1.w = fmaf(m.y, xv.w, a1.w);
        a2.x = fmaf(m.z, xv.x, a2.x); a2.y = fmaf(m.z, xv.y, a2.y);
        a2.z = fmaf(m.z, xv.z, a2.z); a2.w = fmaf(m.z, xv.w, a2.w);
    }

    float4 xv = x4[v * 32 + lane];
    xv.x = (xv.x - mu.x) * rs.x; xv.y = (xv.y - mu.y) * rs.y;
    xv.z = (xv.z - mu.z) * rs.z; xv.w = (xv.w - mu.w) * rs.w;
    float i0 = g_dis[0 * N_NODES + v]; i0 *= i0;
    float i1 = g_dis[1 * N_NODES + v]; i1 *= i1;
    float i2 = g_dis[2 * N_NODES + v]; i2 *= i2;
    a0.x = fmaf(i0, xv.x, a0.x); a0.y = fmaf(i0, xv.y, a0.y);
    a0.z = fmaf(i0, xv.z, a0.z); a0.w = fmaf(i0, xv.w, a0.w);
    a1.x = fmaf(i1, xv.x, a1.x); a1.y = fmaf(i1, xv.y, a1.y);
    a1.z = fmaf(i1, xv.z, a1.z); a1.w = fmaf(i1, xv.w, a1.w);
    a2.x = fmaf(i2, xv.x, a2.x); a2.y = fmaf(i2, xv.y, a2.y);
    a2.z = fmaf(i2, xv.z, a2.z); a2.w = fmaf(i2, xv.w, a2.w);

    float4* o = (float4*)g_agg;
    o[(0 * N_NODES + v) * 32 + lane] = a0;
    o[(1 * N_NODES + v) * 32 + lane] = a1;
    o[(2 * N_NODES + v) * 32 + lane] = a2;
}

// ---------------- tf32 mma.sync GEMM: C[M,N](fp16) = A[M,K] @ W[K,N] (+bias, relu) ------------
// A is fp32 (AH=false) or fp16 (AH=true; fp16->tf32 is exact).
// Block 128x128, 256 threads = 8 warps (2x4), warp tile 64x32, K chunked by 32.
template<bool AH>
__global__ void __launch_bounds__(256) gemm_mma(
    const void* __restrict__ AbaseV, long long Astride,
    const float* __restrict__ Wbase, long long Wstride,
    __half* __restrict__ Cbase, long long Cstride,
    const float* __restrict__ biasBase, int biasStride,
    int M, int N, int K, int doRelu)
{
    __shared__ uint32_t As[128][36];   // [m][k] tf32
    __shared__ uint32_t Bs[32][136];   // [k][n] tf32

    const int t = blockIdx.z;
    const float*  Af = AH ? nullptr : ((const float*)AbaseV + (long long)t * Astride);
    const __half* Ah = AH ? ((const __half*)AbaseV + (long long)t * Astride) : nullptr;
    const float* W = Wbase + (long long)t * Wstride;
    __half*      C = Cbase + (long long)t * Cstride;

    const int tid  = threadIdx.x;
    const int wid  = tid >> 5;
    const int lane = tid & 31;
    const int gid  = lane >> 2;
    const int tig  = lane & 3;
    const int wm0  = (wid & 1) * 64;
    const int wn0  = (wid >> 1) * 32;
    const int bm0  = blockIdx.y * 128;
    const int bn0  = blockIdx.x * 128;

    float acc[4][4][4];
#pragma unroll
    for (int i = 0; i < 4; i++)
#pragma unroll
        for (int j = 0; j < 4; j++)
#pragma unroll
            for (int q = 0; q < 4; q++) acc[i][j][q] = 0.0f;

    const int nch = K >> 5;
    for (int c = 0; c < nch; c++) {
        // A tile: 128 x 32 -> tf32
        if (AH) {
#pragma unroll
            for (int it = 0; it < 2; it++) {
                int idx = tid + it * 256;              // 0..511, 8 halves each
                int r = idx >> 2, c8 = idx & 3;
                const __half* ap = Ah + (long long)(bm0 + r) * K + (c << 5) + c8 * 8;
                uint4 v = *(const uint4*)ap;
                const uint32_t* pw = &v.x;
#pragma unroll
                for (int q = 0; q < 4; q++) {
                    __half2 hh = *(const __half2*)&pw[q];
                    float2 f = __half22float2(hh);
                    As[r][c8 * 8 + q * 2]     = f2tf32(f.x);
                    As[r][c8 * 8 + q * 2 + 1] = f2tf32(f.y);
                }
            }
        } else {
#pragma unroll
            for (int it = 0; it < 4; it++) {
                int idx = tid + it * 256;              // 0..1023 float4s
                int r = idx >> 3, c4 = idx & 7;
                float4 v = *(const float4*)(Af + (long long)(bm0 + r) * K + (c << 5) + c4 * 4);
                uint4 o = make_uint4(f2tf32(v.x), f2tf32(v.y), f2tf32(v.z), f2tf32(v.w));
                *(uint4*)&As[r][c4 * 4] = o;
            }
        }
        // B tile: 32 x 128 floats -> tf32
#pragma unroll
        for (int it = 0; it < 4; it++) {
            int idx = tid + it * 256;
            int k = idx >> 5, n4 = idx & 31;
            float4 v = *(const float4*)(W + (long long)((c << 5) + k) * N + bn0 + n4 * 4);
            uint4 o = make_uint4(f2tf32(v.x), f2tf32(v.y), f2tf32(v.z), f2tf32(v.w));
            *(uint4*)&Bs[k][n4 * 4] = o;
        }
        __syncthreads();

#pragma unroll
        for (int ks = 0; ks < 4; ks++) {
            int kk = ks * 8;
            uint32_t bf[4][2];
#pragma unroll
            for (int nf = 0; nf < 4; nf++) {
                bf[nf][0] = Bs[kk + tig][wn0 + nf * 8 + gid];
                bf[nf][1] = Bs[kk + tig + 4][wn0 + nf * 8 + gid];
            }
#pragma unroll
            for (int mf = 0; mf < 4; mf++) {
                int r = wm0 + mf * 16 + gid;
                uint32_t a0 = As[r][kk + tig];
                uint32_t a1 = As[r + 8][kk + tig];
                uint32_t a2 = As[r][kk + tig + 4];
                uint32_t a3 = As[r + 8][kk + tig + 4];
#pragma unroll
                for (int nf = 0; nf < 4; nf++)
                    mma_tf32(acc[mf][nf], a0, a1, a2, a3, bf[nf][0], bf[nf][1]);
            }
        }
        __syncthreads();
    }

    // epilogue: bias + relu, __half2 stores
#pragma unroll
    for (int mf = 0; mf < 4; mf++) {
        int row = bm0 + wm0 + mf * 16 + gid;
#pragma unroll
        for (int nf = 0; nf < 4; nf++) {
            int col = bn0 + wn0 + nf * 8 + tig * 2;
            float b0 = 0.0f, b1 = 0.0f;
            if (biasBase) {
                const float* bp = biasBase + (long long)t * biasStride + col;
                b0 = bp[0]; b1 = bp[1];
            }
            float o0 = acc[mf][nf][0] + b0;
            float o1 = acc[mf][nf][1] + b1;
            float o2 = acc[mf][nf][2] + b0;
            float o3 = acc[mf][nf][3] + b1;
            if (doRelu) {
                o0 = fmaxf(o0, 0.f); o1 = fmaxf(o1, 0.f);
                o2 = fmaxf(o2, 0.f); o3 = fmaxf(o3, 0.f);
            }
            *(__half2*)(C + (long long)row * N + col)       = __floats2half2_rn(o0, o1);
            *(__half2*)(C + (long long)(row + 8) * N + col) = __floats2half2_rn(o2, o3);
        }
    }
}

// ---------------- layer-2 gather: all 3 types fused, fp16 h2, + output permutation ------------
__global__ void gather2_kernel(const float* __restrict__ b2, float* __restrict__ out) {
    int lane = threadIdx.x & 31;
    int v    = blockIdx.x * 8 + (threadIdx.x >> 5);

    const uint2* __restrict__ h2a = (const uint2*)(g_h2);
    const uint2* __restrict__ h2b = (const uint2*)(g_h2 + (long long)N_NODES * D2);
    const uint2* __restrict__ h2c = (const uint2*)(g_h2 + 2LL * N_NODES * D2);
    int beg = g_rowptr[v];
    int end = g_rowptr[v + 1];

    float4 a0 = make_float4(0.f, 0.f, 0.f, 0.f);
    float4 a1 = make_float4(0.f, 0.f, 0.f, 0.f);
    float4 a2 = make_float4(0.f, 0.f, 0.f, 0.f);

    for (int j = beg; j < end; j++) {
        float4 m = __ldg(&g_meta[j]);
        int src = __float_as_int(m.w);
        uint2 r0 = h2a[src * 32 + lane];
        uint2 r1 = h2b[src * 32 + lane];
        uint2 r2 = h2c[src * 32 + lane];
        float2 f00 = __half22float2(*(__half2*)&r0.x), f01 = __half22float2(*(__half2*)&r0.y);
        float2 f10 = __half22float2(*(__half2*)&r1.x), f11 = __half22float2(*(__half2*)&r1.y);
        float2 f20 = __half22float2(*(__half2*)&r2.x), f21 = __half22float2(*(__half2*)&r2.y);
        a0.x = fmaf(m.x, f00.x, a0.x); a0.y = fmaf(m.x, f00.y, a0.y);
        a0.z = fmaf(m.x, f01.x, a0.z); a0.w = fmaf(m.x, f01.y, a0.w);
        a1.x = fmaf(m.y, f10.x, a1.x); a1.y = fmaf(m.y, f10.y, a1.y);
        a1.z = fmaf(m.y, f11.x, a1.z); a1.w = fmaf(m.y, f11.y, a1.w);
        a2.x = fmaf(m.z, f20.x, a2.x); a2.y = fmaf(m.z, f20.y, a2.y);
        a2.z = fmaf(m.z, f21.x, a2.z); a2.w = fmaf(m.z, f21.y, a2.w);
    }

    float i0 = g_dis[0 * N_NODES + v]; i0 *= i0;
    float i1 = g_dis[1 * N_NODES + v]; i1 *= i1;
    float i2 = g_dis[2 * N_NODES + v]; i2 *= i2;
    uint2 sr0 = h2a[v * 32 + lane];
    uint2 sr1 = h2b[v * 32 + lane];
    uint2 sr2 = h2c[v * 32 + lane];
    float2 s00 = __half22float2(*(__half2*)&sr0.x), s01 = __half22float2(*(__half2*)&sr0.y);
    float2 s10 = __half22float2(*(__half2*)&sr1.x), s11 = __half22float2(*(__half2*)&sr1.y);
    float2 s20 = __half22float2(*(__half2*)&sr2.x), s21 = __half22float2(*(__half2*)&sr2.y);
    float4 bb0 = ((const float4*)(b2 + 0 * D2))[lane];
    float4 bb1 = ((const float4*)(b2 + 1 * D2))[lane];
    float4 bb2 = ((const float4*)(b2 + 2 * D2))[lane];

    a0.x = fmaxf(fmaf(i0, s00.x, a0.x) + bb0.x, 0.f);
    a0.y = fmaxf(fmaf(i0, s00.y, a0.y) + bb0.y, 0.f);
    a0.z = fmaxf(fmaf(i0, s01.x, a0.z) + bb0.z, 0.f);
    a0.w = fmaxf(fmaf(i0, s01.y, a0.w) + bb0.w, 0.f);
    a1.x = fmaxf(fmaf(i1, s10.x, a1.x) + bb1.x, 0.f);
    a1.y = fmaxf(fmaf(i1, s10.y, a1.y) + bb1.y, 0.f);
    a1.z = fmaxf(fmaf(i1, s11.x, a1.z) + bb1.z, 0.f);
    a1.w = fmaxf(fmaf(i1, s11.y, a1.w) + bb1.w, 0.f);
    a2.x = fmaxf(fmaf(i2, s20.x, a2.x) + bb2.x, 0.f);
    a2.y = fmaxf(fmaf(i2, s20.y, a2.y) + bb2.y, 0.f);
    a2.z = fmaxf(fmaf(i2, s21.x, a2.z) + bb2.z, 0.f);
    a2.w = fmaxf(fmaf(i2, s21.y, a2.w) + bb2.w, 0.f);

    int bt = v >> 13;
    int sq = (v >> 9) & 15;
    int vv = v & 511;
    int orow = bt * NNG + vv;
    long long base = ((long long)(orow * SEQ + sq)) * (NT * D2) + lane * 4;
    *(float4*)(out + base)          = a0;
    *(float4*)(out + base + D2)     = a1;
    *(float4*)(out + base + 2 * D2) = a2;
}

// ---------------- launch ----------------
extern "C" void kernel_launch(void* const* d_in, const int* in_sizes, int n_in,
                              void* d_out, int out_size) {
    const float* x  = (const float*)d_in[0];
    const float* ea = (const float*)d_in[1];
    const float* W1 = (const float*)d_in[2];
    const float* b1 = (const float*)d_in[3];
    const float* W2 = (const float*)d_in[4];
    const float* b2 = (const float*)d_in[5];
    const int*   ei = (const int*)d_in[6];
    float* out = (float*)d_out;

    float  *agg;
    __half *h1r, *h2;
    cudaGetSymbolAddress((void**)&agg, g_agg);
    cudaGetSymbolAddress((void**)&h1r, g_h1r);
    cudaGetSymbolAddress((void**)&h2,  g_h2);

    zero_kernel     <<<384, 256>>>();
    stats_kernel    <<<128, 128>>>(x);
    finstats_kernel <<<1, 128>>>();
    hist_kernel     <<<E_EDGES / 256, 256>>>(ei, ea);
    scan_kernel     <<<1, 1024>>>();
    dis_kernel      <<<384, 256>>>();
    fill_kernel     <<<E_EDGES / 256, 256>>>(ei, ea);
    gather0_kernel  <<<N_NODES / 8, 256>>>(x);

    // h1r_t = relu(agg_t @ W1_t + b1_t)   [32768,128]@[128,256] -> fp16
    gemm_mma<false><<<dim3(D1 / 128, N_NODES / 128, NT), 256>>>(
        agg, (long long)N_NODES * F_IN, W1, (long long)F_IN * D1,
        h1r, (long long)N_NODES * D1, b1, D1,
        N_NODES, D1, F_IN, 1);

    // h2_t = h1r_t @ W2_t   [32768,256]@[256,128] -> fp16
    gemm_mma<true><<<dim3(D2 / 128, N_NODES / 128, NT), 256>>>(
        h1r, (long long)N_NODES * D1, W2, (long long)D1 * D2,
        h2, (long long)N_NODES * D2, (const float*)nullptr, 0,
        N_NODES, D2, D1, 0);

    gather2_kernel<<<N_NODES / 8, 256>>>(b2, out);
}

// round 8
// speedup vs baseline: 1.8773x; 1.0258x over previous
#include <cuda_runtime.h>
#include <cuda_fp16.h>
#include <math.h>
#include <stdint.h>

// Problem constants (fixed by setup_inputs)
#define N_NODES 32768
#define E_EDGES 524288
#define F_IN    128
#define D1      256
#define D2      128
#define NT      3
#define SEQ     16
#define NNG     512

// ---------------- scratch (device globals; no allocation allowed) ----------------
__device__ __half g_xh  [N_NODES * F_IN];            // 8 MB normalized x, fp16
__device__ __half g_agg [NT * N_NODES * F_IN];       // 24 MB aggregated xn, fp16
__device__ __half g_h1r [NT * N_NODES * D1];         // 48 MB relu(agg@W1+b1), fp16
__device__ __half g_h2  [NT * N_NODES * D2];         // 24 MB h1r@W2, fp16
__device__ float  g_deg [NT * N_NODES];
__device__ float  g_dis [NT * N_NODES];
__device__ int    g_counts[N_NODES];
__device__ int    g_rowptr[N_NODES + 1];
__device__ int    g_cursor[N_NODES];
__device__ float4 g_meta[E_EDGES];                   // {w0,w1,w2,src-as-float} CSR by dst
__device__ float  g_colsum[F_IN];
__device__ float  g_colsq [F_IN];
__device__ float  g_mean[F_IN];
__device__ float  g_rstd[F_IN];

// ---------------- helpers ----------------
__device__ __forceinline__ uint32_t f2tf32(float f) {
    uint32_t r;
    asm("cvt.rna.tf32.f32 %0, %1;" : "=r"(r) : "f"(f));
    return r;
}
__device__ __forceinline__ void mma_tf32(float* c,
    uint32_t a0, uint32_t a1, uint32_t a2, uint32_t a3,
    uint32_t b0, uint32_t b1)
{
    asm volatile(
        "mma.sync.aligned.m16n8k8.row.col.f32.tf32.tf32.f32 "
        "{%0,%1,%2,%3}, {%4,%5,%6,%7}, {%8,%9}, {%0,%1,%2,%3};"
        : "+f"(c[0]), "+f"(c[1]), "+f"(c[2]), "+f"(c[3])
        : "r"(a0), "r"(a1), "r"(a2), "r"(a3), "r"(b0), "r"(b1));
}
__device__ __forceinline__ uint32_t pack_h2(float a, float b) {
    __half2 h = __floats2half2_rn(a, b);
    return *(uint32_t*)&h;
}

// ---------------- small prep kernels ----------------
__global__ void zero_kernel() {
    int i = blockIdx.x * 256 + threadIdx.x;
    if (i < N_NODES)      g_counts[i] = 0;
    if (i < NT * N_NODES) g_deg[i] = 0.0f;
    if (i < F_IN) { g_colsum[i] = 0.0f; g_colsq[i] = 0.0f; }
}

__global__ void stats_kernel(const float* __restrict__ x) {
    int c  = threadIdx.x;
    int r0 = blockIdx.x * 256;
    float s = 0.0f, q = 0.0f;
    for (int r = 0; r < 256; r++) {
        float v = x[(r0 + r) * F_IN + c];
        s += v; q += v * v;
    }
    atomicAdd(&g_colsum[c], s);
    atomicAdd(&g_colsq[c],  q);
}

__global__ void finstats_kernel() {
    int c = threadIdx.x;
    float n = (float)N_NODES;
    float mean = g_colsum[c] / n;
    float var  = (g_colsq[c] - n * mean * mean) / (n - 1.0f);  // ddof=1
    g_mean[c] = mean;
    g_rstd[c] = rsqrtf(var);
}

// normalize x -> fp16 table
__global__ void xnorm_kernel(const float* __restrict__ x) {
    int i  = blockIdx.x * 256 + threadIdx.x;  // float4 index
    int c4 = (i & 31) * 4;
    float4 v = ((const float4*)x)[i];
    v.x = (v.x - g_mean[c4 + 0]) * g_rstd[c4 + 0];
    v.y = (v.y - g_mean[c4 + 1]) * g_rstd[c4 + 1];
    v.z = (v.z - g_mean[c4 + 2]) * g_rstd[c4 + 2];
    v.w = (v.w - g_mean[c4 + 3]) * g_rstd[c4 + 3];
    uint2 o = make_uint2(pack_h2(v.x, v.y), pack_h2(v.z, v.w));
    ((uint2*)g_xh)[i] = o;
}

__global__ void hist_kernel(const int* __restrict__ ei, const float* __restrict__ ea) {
    int e = blockIdx.x * 256 + threadIdx.x;
    if (e >= E_EDGES) return;
    int dst = ei[E_EDGES + e];
    atomicAdd(&g_counts[dst], 1);
    atomicAdd(&g_deg[0 * N_NODES + dst], fabsf(ea[3 * e + 0]));
    atomicAdd(&g_deg[1 * N_NODES + dst], fabsf(ea[3 * e + 1]));
    atomicAdd(&g_deg[2 * N_NODES + dst], fabsf(ea[3 * e + 2]));
}

__global__ void scan_kernel() {
    __shared__ int sums[1024];
    int tid  = threadIdx.x;
    int base = tid * 32;
    int vals[32];
    int s = 0;
#pragma unroll
    for (int i = 0; i < 32; i++) { int v = g_counts[base + i]; vals[i] = s; s += v; }
    sums[tid] = s;
    __syncthreads();
    for (int off = 1; off < 1024; off <<= 1) {
        int v = (tid >= off) ? sums[tid - off] : 0;
        __syncthreads();
        sums[tid] += v;
        __syncthreads();
    }
    int ex = (tid > 0) ? sums[tid - 1] : 0;
#pragma unroll
    for (int i = 0; i < 32; i++) {
        int p = ex + vals[i];
        g_rowptr[base + i] = p;
        g_cursor[base + i] = p;
    }
    if (tid == 1023) g_rowptr[N_NODES] = sums[1023];
}

__global__ void dis_kernel() {
    int i = blockIdx.x * 256 + threadIdx.x;
    if (i < NT * N_NODES) g_dis[i] = rsqrtf(g_deg[i] + 1.0f);
}

__global__ void fill_kernel(const int* __restrict__ ei, const float* __restrict__ ea) {
    int e = blockIdx.x * 256 + threadIdx.x;
    if (e >= E_EDGES) return;
    int src = ei[e];
    int dst = ei[E_EDGES + e];
    int pos = atomicAdd(&g_cursor[dst], 1);
    float4 m;
    m.x = g_dis[0 * N_NODES + src] * fabsf(ea[3 * e + 0]) * g_dis[0 * N_NODES + dst];
    m.y = g_dis[1 * N_NODES + src] * fabsf(ea[3 * e + 1]) * g_dis[1 * N_NODES + dst];
    m.z = g_dis[2 * N_NODES + src] * fabsf(ea[3 * e + 2]) * g_dis[2 * N_NODES + dst];
    m.w = __int_as_float(src);
    g_meta[pos] = m;
}

// ---------------- fused 3-type aggregation of fp16 xn (gather, atomic-free) ----------------
__global__ void gather0_kernel() {
    int lane = threadIdx.x & 31;
    int v    = blockIdx.x * 8 + (threadIdx.x >> 5);

    const uint2* __restrict__ xh = (const uint2*)g_xh;   // 32 uint2 per row (128 halves)
    int beg = g_rowptr[v];
    int end = g_rowptr[v + 1];

    float4 a0 = make_float4(0.f, 0.f, 0.f, 0.f);
    float4 a1 = make_float4(0.f, 0.f, 0.f, 0.f);
    float4 a2 = make_float4(0.f, 0.f, 0.f, 0.f);

    int j = beg;
    for (; j + 1 < end; j += 2) {
        float4 mA = __ldg(&g_meta[j]);
        float4 mB = __ldg(&g_meta[j + 1]);
        uint2 rA = xh[__float_as_int(mA.w) * 32 + lane];
        uint2 rB = xh[__float_as_int(mB.w) * 32 + lane];
        float2 fA0 = __half22float2(*(__half2*)&rA.x);
        float2 fA1 = __half22float2(*(__half2*)&rA.y);
        float2 fB0 = __half22float2(*(__half2*)&rB.x);
        float2 fB1 = __half22float2(*(__half2*)&rB.y);
        a0.x = fmaf(mA.x, fA0.x, a0.x); a0.y = fmaf(mA.x, fA0.y, a0.y);
        a0.z = fmaf(mA.x, fA1.x, a0.z); a0.w = fmaf(mA.x, fA1.y, a0.w);
        a1.x = fmaf(mA.y, fA0.x, a1.x); a1.y = fmaf(mA.y, fA0.y, a1.y);
        a1.z = fmaf(mA.y, fA1.x, a1.z); a1.w = fmaf(mA.y, fA1.y, a1.w);
        a2.x = fmaf(mA.z, fA0.x, a2.x); a2.y = fmaf(mA.z, fA0.y, a2.y);
        a2.z = fmaf(mA.z, fA1.x, a2.z); a2.w = fmaf(mA.z, fA1.y, a2.w);
        a0.x = fmaf(mB.x, fB0.x, a0.x); a0.y = fmaf(mB.x, fB0.y, a0.y);
        a0.z = fmaf(mB.x, fB1.x, a0.z); a0.w = fmaf(mB.x, fB1.y, a0.w);
        a1.x = fmaf(mB.y, fB0.x, a1.x); a1.y = fmaf(mB.y, fB0.y, a1.y);
        a1.z = fmaf(mB.y, fB1.x, a1.z); a1.w = fmaf(mB.y, fB1.y, a1.w);
        a2.x = fmaf(mB.z, fB0.x, a2.x); a2.y = fmaf(mB.z, fB0.y, a2.y);
        a2.z = fmaf(mB.z, fB1.x, a2.z); a2.w = fmaf(mB.z, fB1.y, a2.w);
    }
    if (j < end) {
        float4 m = __ldg(&g_meta[j]);
        uint2 r = xh[__float_as_int(m.w) * 32 + lane];
        float2 f0 = __half22float2(*(__half2*)&r.x);
        float2 f1 = __half22float2(*(__half2*)&r.y);
        a0.x = fmaf(m.x, f0.x, a0.x); a0.y = fmaf(m.x, f0.y, a0.y);
        a0.z = fmaf(m.x, f1.x, a0.z); a0.w = fmaf(m.x, f1.y, a0.w);
        a1.x = fmaf(m.y, f0.x, a1.x); a1.y = fmaf(m.y, f0.y, a1.y);
        a1.z = fmaf(m.y, f1.x, a1.z); a1.w = fmaf(m.y, f1.y, a1.w);
        a2.x = fmaf(m.z, f0.x, a2.x); a2.y = fmaf(m.z, f0.y, a2.y);
        a2.z = fmaf(m.z, f1.x, a2.z); a2.w = fmaf(m.z, f1.y, a2.w);
    }

    uint2 rv = xh[v * 32 + lane];
    float2 v0 = __half22float2(*(__half2*)&rv.x);
    float2 v1 = __half22float2(*(__half2*)&rv.y);
    float i0 = g_dis[0 * N_NODES + v]; i0 *= i0;
    float i1 = g_dis[1 * N_NODES + v]; i1 *= i1;
    float i2 = g_dis[2 * N_NODES + v]; i2 *= i2;
    a0.x = fmaf(i0, v0.x, a0.x); a0.y = fmaf(i0, v0.y, a0.y);
    a0.z = fmaf(i0, v1.x, a0.z); a0.w = fmaf(i0, v1.y, a0.w);
    a1.x = fmaf(i1, v0.x, a1.x); a1.y = fmaf(i1, v0.y, a1.y);
    a1.z = fmaf(i1, v1.x, a1.z); a1.w = fmaf(i1, v1.y, a1.w);
    a2.x = fmaf(i2, v0.x, a2.x); a2.y = fmaf(i2, v0.y, a2.y);
    a2.z = fmaf(i2, v1.x, a2.z); a2.w = fmaf(i2, v1.y, a2.w);

    uint2* o = (uint2*)g_agg;
    o[(0 * N_NODES + v) * 32 + lane] = make_uint2(pack_h2(a0.x, a0.y), pack_h2(a0.z, a0.w));
    o[(1 * N_NODES + v) * 32 + lane] = make_uint2(pack_h2(a1.x, a1.y), pack_h2(a1.z, a1.w));
    o[(2 * N_NODES + v) * 32 + lane] = make_uint2(pack_h2(a2.x, a2.y), pack_h2(a2.z, a2.w));
}

// ---------------- tf32 mma.sync GEMM: C[M,N](fp16) = A(fp16)[M,K] @ W(fp32)[K,N] ----------------
// fp16 -> tf32 is exact. Block 128x128, 256 threads = 8 warps (2x4), warp tile 64x32, K chunk 32.
__global__ void __launch_bounds__(256) gemm_mma(
    const __half* __restrict__ Abase, long long Astride,
    const float* __restrict__ Wbase, long long Wstride,
    __half* __restrict__ Cbase, long long Cstride,
    const float* __restrict__ biasBase, int biasStride,
    int M, int N, int K, int doRelu)
{
    __shared__ uint32_t As[128][36];   // [m][k] tf32
    __shared__ uint32_t Bs[32][136];   // [k][n] tf32

    const int t = blockIdx.z;
    const __half* A = Abase + (long long)t * Astride;
    const float*  W = Wbase + (long long)t * Wstride;
    __half*       C = Cbase + (long long)t * Cstride;

    const int tid  = threadIdx.x;
    const int wid  = tid >> 5;
    const int lane = tid & 31;
    const int gid  = lane >> 2;
    const int tig  = lane & 3;
    const int wm0  = (wid & 1) * 64;
    const int wn0  = (wid >> 1) * 32;
    const int bm0  = blockIdx.y * 128;
    const int bn0  = blockIdx.x * 128;

    float acc[4][4][4];
#pragma unroll
    for (int i = 0; i < 4; i++)
#pragma unroll
        for (int j = 0; j < 4; j++)
#pragma unroll
            for (int q = 0; q < 4; q++) acc[i][j][q] = 0.0f;

    const int nch = K >> 5;
    for (int c = 0; c < nch; c++) {
        // A tile: 128 x 32 halves -> tf32
#pragma unroll
        for (int it = 0; it < 2; it++) {
            int idx = tid + it * 256;              // 0..511, 8 halves each
            int r = idx >> 2, c8 = idx & 3;
            const __half* ap = A + (long long)(bm0 + r) * K + (c << 5) + c8 * 8;
            uint4 v = *(const uint4*)ap;
            const uint32_t* pw = &v.x;
#pragma unroll
            for (int q = 0; q < 4; q++) {
                float2 f = __half22float2(*(const __half2*)&pw[q]);
                As[r][c8 * 8 + q * 2]     = f2tf32(f.x);
                As[r][c8 * 8 + q * 2 + 1] = f2tf32(f.y);
            }
        }
        // B tile: 32 x 128 floats -> tf32
#pragma unroll
        for (int it = 0; it < 4; it++) {
            int idx = tid + it * 256;
            int k = idx >> 5, n4 = idx & 31;
            float4 v = *(const float4*)(W + (long long)((c << 5) + k) * N + bn0 + n4 * 4);
            uint4 o = make_uint4(f2tf32(v.x), f2tf32(v.y), f2tf32(v.z), f2tf32(v.w));
            *(uint4*)&Bs[k][n4 * 4] = o;
        }
        __syncthreads();

#pragma unroll
        for (int ks = 0; ks < 4; ks++) {
            int kk = ks * 8;
            uint32_t bf[4][2];
#pragma unroll
            for (int nf = 0; nf < 4; nf++) {
                bf[nf][0] = Bs[kk + tig][wn0 + nf * 8 + gid];
                bf[nf][1] = Bs[kk + tig + 4][wn0 + nf * 8 + gid];
            }
#pragma unroll
            for (int mf = 0; mf < 4; mf++) {
                int r = wm0 + mf * 16 + gid;
                uint32_t a0 = As[r][kk + tig];
                uint32_t a1 = As[r + 8][kk + tig];
                uint32_t a2 = As[r][kk + tig + 4];
                uint32_t a3 = As[r + 8][kk + tig + 4];
#pragma unroll
                for (int nf = 0; nf < 4; nf++)
                    mma_tf32(acc[mf][nf], a0, a1, a2, a3, bf[nf][0], bf[nf][1]);
            }
        }
        __syncthreads();
    }

    // epilogue: bias + relu, __half2 stores
#pragma unroll
    for (int mf = 0; mf < 4; mf++) {
        int row = bm0 + wm0 + mf * 16 + gid;
#pragma unroll
        for (int nf = 0; nf < 4; nf++) {
            int col = bn0 + wn0 + nf * 8 + tig * 2;
            float b0 = 0.0f, b1 = 0.0f;
            if (biasBase) {
                const float* bp = biasBase + (long long)t * biasStride + col;
                b0 = bp[0]; b1 = bp[1];
            }
            float o0 = acc[mf][nf][0] + b0;
            float o1 = acc[mf][nf][1] + b1;
            float o2 = acc[mf][nf][2] + b0;
            float o3 = acc[mf][nf][3] + b1;
            if (doRelu) {
                o0 = fmaxf(o0, 0.f); o1 = fmaxf(o1, 0.f);
                o2 = fmaxf(o2, 0.f); o3 = fmaxf(o3, 0.f);
            }
            *(__half2*)(C + (long long)row * N + col)       = __floats2half2_rn(o0, o1);
            *(__half2*)(C + (long long)(row + 8) * N + col) = __floats2half2_rn(o2, o3);
        }
    }
}

// ---------------- layer-2 gather: all 3 types fused, fp16 h2, + output permutation ------------
__global__ void gather2_kernel(const float* __restrict__ b2, float* __restrict__ out) {
    int lane = threadIdx.x & 31;
    int v    = blockIdx.x * 8 + (threadIdx.x >> 5);

    const uint2* __restrict__ h2a = (const uint2*)(g_h2);
    const uint2* __restrict__ h2b = (const uint2*)(g_h2 + (long long)N_NODES * D2);
    const uint2* __restrict__ h2c = (const uint2*)(g_h2 + 2LL * N_NODES * D2);
    int beg = g_rowptr[v];
    int end = g_rowptr[v + 1];

    float4 a0 = make_float4(0.f, 0.f, 0.f, 0.f);
    float4 a1 = make_float4(0.f, 0.f, 0.f, 0.f);
    float4 a2 = make_float4(0.f, 0.f, 0.f, 0.f);

    for (int j = beg; j < end; j++) {
        float4 m = __ldg(&g_meta[j]);
        int src = __float_as_int(m.w);
        uint2 r0 = h2a[src * 32 + lane];
        uint2 r1 = h2b[src * 32 + lane];
        uint2 r2 = h2c[src * 32 + lane];
        float2 f00 = __half22float2(*(__half2*)&r0.x), f01 = __half22float2(*(__half2*)&r0.y);
        float2 f10 = __half22float2(*(__half2*)&r1.x), f11 = __half22float2(*(__half2*)&r1.y);
        float2 f20 = __half22float2(*(__half2*)&r2.x), f21 = __half22float2(*(__half2*)&r2.y);
        a0.x = fmaf(m.x, f00.x, a0.x); a0.y = fmaf(m.x, f00.y, a0.y);
        a0.z = fmaf(m.x, f01.x, a0.z); a0.w = fmaf(m.x, f01.y, a0.w);
        a1.x = fmaf(m.y, f10.x, a1.x); a1.y = fmaf(m.y, f10.y, a1.y);
        a1.z = fmaf(m.y, f11.x, a1.z); a1.w = fmaf(m.y, f11.y, a1.w);
        a2.x = fmaf(m.z, f20.x, a2.x); a2.y = fmaf(m.z, f20.y, a2.y);
        a2.z = fmaf(m.z, f21.x, a2.z); a2.w = fmaf(m.z, f21.y, a2.w);
    }

    float i0 = g_dis[0 * N_NODES + v]; i0 *= i0;
    float i1 = g_dis[1 * N_NODES + v]; i1 *= i1;
    float i2 = g_dis[2 * N_NODES + v]; i2 *= i2;
    uint2 sr0 = h2a[v * 32 + lane];
    uint2 sr1 = h2b[v * 32 + lane];
    uint2 sr2 = h2c[v * 32 + lane];
    float2 s00 = __half22float2(*(__half2*)&sr0.x), s01 = __half22float2(*(__half2*)&sr0.y);
    float2 s10 = __half22float2(*(__half2*)&sr1.x), s11 = __half22float2(*(__half2*)&sr1.y);
    float2 s20 = __half22float2(*(__half2*)&sr2.x), s21 = __half22float2(*(__half2*)&sr2.y);
    float4 bb0 = ((const float4*)(b2 + 0 * D2))[lane];
    float4 bb1 = ((const float4*)(b2 + 1 * D2))[lane];
    float4 bb2 = ((const float4*)(b2 + 2 * D2))[lane];

    a0.x = fmaxf(fmaf(i0, s00.x, a0.x) + bb0.x, 0.f);
    a0.y = fmaxf(fmaf(i0, s00.y, a0.y) + bb0.y, 0.f);
    a0.z = fmaxf(fmaf(i0, s01.x, a0.z) + bb0.z, 0.f);
    a0.w = fmaxf(fmaf(i0, s01.y, a0.w) + bb0.w, 0.f);
    a1.x = fmaxf(fmaf(i1, s10.x, a1.x) + bb1.x, 0.f);
    a1.y = fmaxf(fmaf(i1, s10.y, a1.y) + bb1.y, 0.f);
    a1.z = fmaxf(fmaf(i1, s11.x, a1.z) + bb1.z, 0.f);
    a1.w = fmaxf(fmaf(i1, s11.y, a1.w) + bb1.w, 0.f);
    a2.x = fmaxf(fmaf(i2, s20.x, a2.x) + bb2.x, 0.f);
    a2.y = fmaxf(fmaf(i2, s20.y, a2.y) + bb2.y, 0.f);
    a2.z = fmaxf(fmaf(i2, s21.x, a2.z) + bb2.z, 0.f);
    a2.w = fmaxf(fmaf(i2, s21.y, a2.w) + bb2.w, 0.f);

    int bt = v >> 13;
    int sq = (v >> 9) & 15;
    int vv = v & 511;
    int orow = bt * NNG + vv;
    long long base = ((long long)(orow * SEQ + sq)) * (NT * D2) + lane * 4;
    *(float4*)(out + base)          = a0;
    *(float4*)(out + base + D2)     = a1;
    *(float4*)(out + base + 2 * D2) = a2;
}

// ---------------- launch ----------------
extern "C" void kernel_launch(void* const* d_in, const int* in_sizes, int n_in,
                              void* d_out, int out_size) {
    const float* x  = (const float*)d_in[0];
    const float* ea = (const float*)d_in[1];
    const float* W1 = (const float*)d_in[2];
    const float* b1 = (const float*)d_in[3];
    const float* W2 = (const float*)d_in[4];
    const float* b2 = (const float*)d_in[5];
    const int*   ei = (const int*)d_in[6];
    float* out = (float*)d_out;

    __half *agg, *h1r, *h2;
    cudaGetSymbolAddress((void**)&agg, g_agg);
    cudaGetSymbolAddress((void**)&h1r, g_h1r);
    cudaGetSymbolAddress((void**)&h2,  g_h2);

    zero_kernel     <<<384, 256>>>();
    stats_kernel    <<<128, 128>>>(x);
    finstats_kernel <<<1, 128>>>();
    xnorm_kernel    <<<4096, 256>>>(x);
    hist_kernel     <<<E_EDGES / 256, 256>>>(ei, ea);
    scan_kernel     <<<1, 1024>>>();
    dis_kernel      <<<384, 256>>>();
    fill_kernel     <<<E_EDGES / 256, 256>>>(ei, ea);
    gather0_kernel  <<<N_NODES / 8, 256>>>();

    // h1r_t = relu(agg_t @ W1_t + b1_t)   [32768,128]@[128,256] -> fp16
    gemm_mma<<<dim3(D1 / 128, N_NODES / 128, NT), 256>>>(
        agg, (long long)N_NODES * F_IN, W1, (long long)F_IN * D1,
        h1r, (long long)N_NODES * D1, b1, D1,
        N_NODES, D1, F_IN, 1);

    // h2_t = h1r_t @ W2_t   [32768,256]@[256,128] -> fp16
    gemm_mma<<<dim3(D2 / 128, N_NODES / 128, NT), 256>>>(
        h1r, (long long)N_NODES * D1, W2, (long long)D1 * D2,
        h2, (long long)N_NODES * D2, (const float*)nullptr, 0,
        N_NODES, D2, D1, 0);

    gather2_kernel<<<N_NODES / 8, 256>>>(b2, out);
}